// round 10
// baseline (speedup 1.0000x reference)
#include <cuda_runtime.h>
#include <cuda_fp16.h>
#include <cstdint>

#define Bb   4
#define Nn   2048
#define DM   512
#define Hh   8
#define DH   64
#define SCALE_F 0.125f
#define LOG2E 1.4426950408889634f

#define GEMM_SMEM  (2 * 6912 * 4)   // 55296 B
#define FLASH_SMEM 32768            // 2 stages x (K 8KB + V 8KB), fp16 packed

// ---- scratch (static __device__, allocation-free) ----
__device__ float g_G [(size_t)Bb * Nn * Nn];
__device__ float g_Q [(size_t)Bb * Hh * Nn * DH];
__device__ float g_K [(size_t)Bb * Hh * Nn * DH];
__device__ float g_V [(size_t)Bb * Hh * Nn * DH];
__device__ float g_AO[(size_t)Bb * Nn * DM];

// ---- helpers ----
__device__ __forceinline__ unsigned f2tf(float x) {
    unsigned r;
    asm("cvt.rna.tf32.f32 %0, %1;" : "=r"(r) : "f"(x));
    return r;
}
__device__ __forceinline__ float f2tff(float x) { return __uint_as_float(f2tf(x)); }
__device__ __forceinline__ unsigned u(float x) { return __float_as_uint(x); }
__device__ __forceinline__ unsigned pack2(float lo, float hi) {
    __half2 h = __floats2half2_rn(lo, hi);
    return *reinterpret_cast<unsigned*>(&h);
}

__device__ __forceinline__ void mma_tf32(float& d0, float& d1, float& d2, float& d3,
                                         unsigned a0, unsigned a1, unsigned a2, unsigned a3,
                                         unsigned b0, unsigned b1) {
    asm volatile(
        "mma.sync.aligned.m16n8k8.row.col.f32.tf32.tf32.f32 "
        "{%0,%1,%2,%3}, {%4,%5,%6,%7}, {%8,%9}, {%0,%1,%2,%3};"
        : "+f"(d0), "+f"(d1), "+f"(d2), "+f"(d3)
        : "r"(a0), "r"(a1), "r"(a2), "r"(a3), "r"(b0), "r"(b1));
}

__device__ __forceinline__ void mma_f16(float& d0, float& d1, float& d2, float& d3,
                                        unsigned a0, unsigned a1, unsigned a2, unsigned a3,
                                        unsigned b0, unsigned b1) {
    asm volatile(
        "mma.sync.aligned.m16n8k16.row.col.f32.f16.f16.f32 "
        "{%0,%1,%2,%3}, {%4,%5,%6,%7}, {%8,%9}, {%0,%1,%2,%3};"
        : "+f"(d0), "+f"(d1), "+f"(d2), "+f"(d3)
        : "r"(a0), "r"(a1), "r"(a2), "r"(a3), "r"(b0), "r"(b1));
}

// ============================================================
// Kernel 0: gate precompute  G = log2(sigmoid(w*SC + b) + 1e-8)
// ============================================================
__global__ void gate_kernel(const float4* __restrict__ SC,
                            const float* __restrict__ gw,
                            const float* __restrict__ gb) {
    int i = blockIdx.x * 256 + threadIdx.x;
    float w = __ldg(gw), b = __ldg(gb);
    float4 s = SC[i];
    float4 r;
    r.x = __log2f(__fdividef(1.f, 1.f + __expf(-(s.x * w + b))) + 1e-8f);
    r.y = __log2f(__fdividef(1.f, 1.f + __expf(-(s.y * w + b))) + 1e-8f);
    r.z = __log2f(__fdividef(1.f, 1.f + __expf(-(s.z * w + b))) + 1e-8f);
    r.w = __log2f(__fdividef(1.f, 1.f + __expf(-(s.w * w + b))) + 1e-8f);
    reinterpret_cast<float4*>(g_G)[i] = r;
}

// ============================================================
// Kernel 1: tf32 GEMM (unchanged from R8)
// ============================================================
__global__ __launch_bounds__(256) void gemm512(const float* __restrict__ Aext,
                                               const float* __restrict__ Wa,
                                               const float* __restrict__ biasa,
                                               const float* __restrict__ Wb,
                                               const float* __restrict__ biasb,
                                               float* __restrict__ Cext,
                                               int amode, int cmode) {
    extern __shared__ float dyn[];

    const float* A = amode ? g_AO : Aext;
    const float* W    = Wa;
    const float* bias = biasa;
    float* C;
    if      (cmode == 0) C = g_Q;
    else if (cmode == 3) C = Cext;
    else {
        if (blockIdx.x >= 8) { W = Wb; bias = biasb; C = g_V; }
        else                 {                        C = g_K; }
    }
    const bool scatter = (cmode != 3);

    int tid  = threadIdx.x;
    int warp = tid >> 5, lane = tid & 31;
    int g = lane >> 2, tg = lane & 3;
    int wm = warp >> 1, wn = warp & 1;
    int mbase = blockIdx.y * 128, nbase = (blockIdx.x & 7) * 64;

    int ar = tid >> 3, acc_ = (tid & 7) * 4;
    int ap = ar * 36 + (acc_ >> 2);
    int br = tid >> 3;
    int bp = br * 36 + (acc_ >> 2);

    float acc[2][4][4];
#pragma unroll
    for (int mt = 0; mt < 2; ++mt)
#pragma unroll
        for (int nt = 0; nt < 4; ++nt)
#pragma unroll
            for (int i = 0; i < 4; ++i) acc[mt][nt][i] = 0.f;

    {
        float* As = dyn;
        float* Bs = dyn + 4608;
#pragma unroll
        for (int i = 0; i < 4; ++i) {
            float4 v = *reinterpret_cast<const float4*>(A + (size_t)(mbase + ar + i * 32) * 512 + acc_);
            int p = ap + i * 32 * 36;
            As[p] = f2tff(v.x); As[p + 8] = f2tff(v.y); As[p + 16] = f2tff(v.z); As[p + 24] = f2tff(v.w);
        }
#pragma unroll
        for (int i = 0; i < 2; ++i) {
            float4 v = *reinterpret_cast<const float4*>(W + (size_t)(nbase + br + i * 32) * 512 + acc_);
            int p = bp + i * 32 * 36;
            Bs[p] = f2tff(v.x); Bs[p + 8] = f2tff(v.y); Bs[p + 16] = f2tff(v.z); Bs[p + 24] = f2tff(v.w);
        }
    }
    __syncthreads();

    for (int kt = 0; kt < 16; ++kt) {
        float* As = dyn + (kt & 1) * 6912;
        float* Bs = As + 4608;
        float* AsN = dyn + ((kt + 1) & 1) * 6912;
        float* BsN = AsN + 4608;

        float4 pa[4], pb[2];
        if (kt < 15) {
            int k0 = (kt + 1) * 32;
#pragma unroll
            for (int i = 0; i < 4; ++i)
                pa[i] = *reinterpret_cast<const float4*>(A + (size_t)(mbase + ar + i * 32) * 512 + k0 + acc_);
#pragma unroll
            for (int i = 0; i < 2; ++i)
                pb[i] = *reinterpret_cast<const float4*>(W + (size_t)(nbase + br + i * 32) * 512 + k0 + acc_);
        }

        unsigned a[2][4][4];
#pragma unroll
        for (int mt = 0; mt < 2; ++mt) {
            const float4* p0 = reinterpret_cast<const float4*>(As + (wm * 32 + mt * 16 + g    ) * 36 + tg * 8);
            const float4* p1 = reinterpret_cast<const float4*>(As + (wm * 32 + mt * 16 + g + 8) * 36 + tg * 8);
            float4 f0 = p0[0], f1 = p0[1];
            float4 f2 = p1[0], f3 = p1[1];
            a[mt][0][0] = u(f0.x); a[mt][0][1] = u(f2.x); a[mt][0][2] = u(f0.y); a[mt][0][3] = u(f2.y);
            a[mt][1][0] = u(f0.z); a[mt][1][1] = u(f2.z); a[mt][1][2] = u(f0.w); a[mt][1][3] = u(f2.w);
            a[mt][2][0] = u(f1.x); a[mt][2][1] = u(f3.x); a[mt][2][2] = u(f1.y); a[mt][2][3] = u(f3.y);
            a[mt][3][0] = u(f1.z); a[mt][3][1] = u(f3.z); a[mt][3][2] = u(f1.w); a[mt][3][3] = u(f3.w);
        }

#pragma unroll
        for (int kcp = 0; kcp < 2; ++kcp) {
            int kc0 = kcp * 2, kc1 = kcp * 2 + 1;
#pragma unroll
            for (int nt = 0; nt < 4; ++nt) {
                float4 f = reinterpret_cast<const float4*>(Bs + (wn * 32 + nt * 8 + g) * 36 + tg * 8)[kcp];
                mma_tf32(acc[0][nt][0], acc[0][nt][1], acc[0][nt][2], acc[0][nt][3],
                         a[0][kc0][0], a[0][kc0][1], a[0][kc0][2], a[0][kc0][3], u(f.x), u(f.y));
                mma_tf32(acc[1][nt][0], acc[1][nt][1], acc[1][nt][2], acc[1][nt][3],
                         a[1][kc0][0], a[1][kc0][1], a[1][kc0][2], a[1][kc0][3], u(f.x), u(f.y));
                mma_tf32(acc[0][nt][0], acc[0][nt][1], acc[0][nt][2], acc[0][nt][3],
                         a[0][kc1][0], a[0][kc1][1], a[0][kc1][2], a[0][kc1][3], u(f.z), u(f.w));
                mma_tf32(acc[1][nt][0], acc[1][nt][1], acc[1][nt][2], acc[1][nt][3],
                         a[1][kc1][0], a[1][kc1][1], a[1][kc1][2], a[1][kc1][3], u(f.z), u(f.w));
            }
        }

        if (kt < 15) {
#pragma unroll
            for (int i = 0; i < 4; ++i) {
                int p = ap + i * 32 * 36;
                AsN[p] = f2tff(pa[i].x); AsN[p + 8] = f2tff(pa[i].y);
                AsN[p + 16] = f2tff(pa[i].z); AsN[p + 24] = f2tff(pa[i].w);
            }
#pragma unroll
            for (int i = 0; i < 2; ++i) {
                int p = bp + i * 32 * 36;
                BsN[p] = f2tff(pb[i].x); BsN[p + 8] = f2tff(pb[i].y);
                BsN[p + 16] = f2tff(pb[i].z); BsN[p + 24] = f2tff(pb[i].w);
            }
        }
        __syncthreads();
    }

#pragma unroll
    for (int mt = 0; mt < 2; ++mt)
#pragma unroll
        for (int nt = 0; nt < 4; ++nt) {
            int col = nbase + wn * 32 + nt * 8 + 2 * tg;
            float b0 = bias[col], b1 = bias[col + 1];
            int r0 = mbase + wm * 32 + mt * 16 + g;
            int r1 = r0 + 8;
            float v00 = acc[mt][nt][0] + b0, v01 = acc[mt][nt][1] + b1;
            float v10 = acc[mt][nt][2] + b0, v11 = acc[mt][nt][3] + b1;
            if (scatter) {
                int h = col >> 6, d = col & 63;
                {
                    int b = r0 >> 11, n = r0 & 2047;
                    float* p = C + (size_t)(((b << 3) + h) * 2048 + n) * 64 + d;
                    *reinterpret_cast<float2*>(p) = make_float2(v00, v01);
                }
                {
                    int b = r1 >> 11, n = r1 & 2047;
                    float* p = C + (size_t)(((b << 3) + h) * 2048 + n) * 64 + d;
                    *reinterpret_cast<float2*>(p) = make_float2(v10, v11);
                }
            } else {
                *reinterpret_cast<float2*>(C + (size_t)r0 * 512 + col) = make_float2(v00, v01);
                *reinterpret_cast<float2*>(C + (size_t)r1 * 512 + col) = make_float2(v10, v11);
            }
        }
}

// ============================================================
// Kernel 2: fp16 flash attention (m16n8k16), BM=64, BN=64,
//  128 threads, double-buffered.  smem layout per stage (b32):
//    K: 64 rows x 32 b32 (d-pairs), V^T: 64 d-rows x 32 b32 (key-pairs)
//  pair p stored at col (p&3)*8+(p>>2), float4-XOR-swizzled by (row&7).
//  Fragment reads: 1 LDS.128 yields b0/b1 for two k16-steps.
//  P re-fragmentation: C-layout of S == A-layout of P (no shuffles).
// ============================================================
__global__ __launch_bounds__(128, 2) void flash_kernel() {
    extern __shared__ float smf[];
    unsigned* smU = reinterpret_cast<unsigned*>(smf);

    int tid = threadIdx.x, w = tid >> 5, lane = tid & 31;
    int g = lane >> 2, tg = lane & 3;
    int h = blockIdx.x, qt = blockIdx.y, bz = blockIdx.z;
    int bh = bz * 8 + h;
    const float* Qb = g_Q + (size_t)bh * Nn * DH;
    const float* Kb = g_K + (size_t)bh * Nn * DH;
    const float* Vb = g_V + (size_t)bh * Nn * DH;
    int q0 = qt * 64;

    // ---- K staging map: sK in 0..7, intra-warp delta 2 (bank proof) ----
    int sK  = ((w >> 1) << 2) + (w & 1) + ((lane >> 4) << 1);
    int m   = lane & 15;
    int scc = m * 4;
    int p0  = 2 * m;
    int kx0 = ((p0 & 3) << 3) + (p0 >> 2);            // b32 col of pair p0
    int kx1 = (((p0 + 1) & 3) << 3) + ((p0 + 1) >> 2);
    // ---- V staging map: rp = lane (key pair), cg = w (16 d cols) ----
    int rp  = lane;
    int vx  = ((rp & 3) << 3) + (rp >> 2);

    // ---- stage Q tile [64,64] fp32 (stride 68) and read fp16 fragments ----
#pragma unroll
    for (int i = 0; i < 8; ++i) {
        int idx = tid + i * 128;
        int r = idx >> 4, c = (idx & 15) * 4;
        float4 v = *reinterpret_cast<const float4*>(Qb + (size_t)(q0 + r) * 64 + c);
        *reinterpret_cast<float4*>(smf + r * 68 + c) = v;
    }
    __syncthreads();
    unsigned qa[4][4];
    {
        int r0 = w * 16 + g, r1 = r0 + 8;
#pragma unroll
        for (int kc = 0; kc < 4; ++kc) {
            float2 v0 = *reinterpret_cast<const float2*>(smf + r0 * 68 + kc * 16 + 2 * tg);
            float2 v1 = *reinterpret_cast<const float2*>(smf + r1 * 68 + kc * 16 + 2 * tg);
            float2 v2 = *reinterpret_cast<const float2*>(smf + r0 * 68 + kc * 16 + 2 * tg + 8);
            float2 v3 = *reinterpret_cast<const float2*>(smf + r1 * 68 + kc * 16 + 2 * tg + 8);
            qa[kc][0] = pack2(v0.x, v0.y);
            qa[kc][1] = pack2(v1.x, v1.y);
            qa[kc][2] = pack2(v2.x, v2.y);
            qa[kc][3] = pack2(v3.x, v3.y);
        }
    }
    __syncthreads();

    // ---- stage K/V kt=0 into stage 0 ----
    {
        unsigned* K0 = smU;
        unsigned* V0 = smU + 2048;
#pragma unroll
        for (int i = 0; i < 8; ++i) {
            int r = sK + 8 * i;
            float4 v = *reinterpret_cast<const float4*>(Kb + (size_t)r * 64 + scc);
            int xr = (r & 7) << 2;
            K0[r * 32 + (kx0 ^ xr)] = pack2(v.x, v.y);
            K0[r * 32 + (kx1 ^ xr)] = pack2(v.z, v.w);
        }
#pragma unroll
        for (int j = 0; j < 4; ++j) {
            float4 va = *reinterpret_cast<const float4*>(Vb + (size_t)(2 * rp    ) * 64 + 16 * w + 4 * j);
            float4 vb = *reinterpret_cast<const float4*>(Vb + (size_t)(2 * rp + 1) * 64 + 16 * w + 4 * j);
            int d = 16 * w + 4 * j;
            V0[(d    ) * 32 + (vx ^ (((d    ) & 7) << 2))] = pack2(va.x, vb.x);
            V0[(d + 1) * 32 + (vx ^ (((d + 1) & 7) << 2))] = pack2(va.y, vb.y);
            V0[(d + 2) * 32 + (vx ^ (((d + 2) & 7) << 2))] = pack2(va.z, vb.z);
            V0[(d + 3) * 32 + (vx ^ (((d + 3) & 7) << 2))] = pack2(va.w, vb.w);
        }
    }
    __syncthreads();

    float accO[8][4];
#pragma unroll
    for (int ot = 0; ot < 8; ++ot)
#pragma unroll
        for (int i = 0; i < 4; ++i) accO[ot][i] = 0.f;
    float m0 = -1e30f, m1 = -1e30f, l0 = 0.f, l1 = 0.f;

    const float* G0 = g_G + ((size_t)bz * Nn + (q0 + w * 16 + g)) * Nn;
    const float* G1 = G0 + (size_t)8 * Nn;
    const float SL2 = SCALE_F * LOG2E;

    for (int kt = 0; kt < 32; ++kt) {
        unsigned* Ks = smU + (kt & 1) * 4096;
        unsigned* Vs = Ks + 2048;
        unsigned* KsN = smU + ((kt + 1) & 1) * 4096;
        unsigned* VsN = KsN + 2048;

        const float* Kt = Kb + (size_t)(kt + 1) * 4096;
        const float* Vt = Vb + (size_t)(kt + 1) * 4096;

        // prefetch next K tile (regs live across QK only)
        float4 pk[8];
        if (kt < 31) {
#pragma unroll
            for (int i = 0; i < 8; ++i)
                pk[i] = *reinterpret_cast<const float4*>(Kt + (size_t)(sK + 8 * i) * 64 + scc);
        }

        // prefetch gate rows (consumed after QK)
        float2 gA[8], gB[8];
        {
            int cbase = kt * 64 + 2 * tg;
#pragma unroll
            for (int nt = 0; nt < 8; ++nt) {
                gA[nt] = *reinterpret_cast<const float2*>(G0 + cbase + nt * 8);
                gB[nt] = *reinterpret_cast<const float2*>(G1 + cbase + nt * 8);
            }
        }

        // ---- S = Q K^T : 2 kc-pairs x 8 nt, 8 independent chains ----
        float sacc[8][4];
#pragma unroll
        for (int nt = 0; nt < 8; ++nt)
#pragma unroll
            for (int i = 0; i < 4; ++i) sacc[nt][i] = 0.f;
#pragma unroll
        for (int kcp = 0; kcp < 2; ++kcp) {
            int F = 2 * tg + kcp;
#pragma unroll
            for (int nt = 0; nt < 8; ++nt) {
                int r = nt * 8 + g;
                float4 f = *reinterpret_cast<const float4*>(Ks + r * 32 + ((F ^ g) << 2));
                mma_f16(sacc[nt][0], sacc[nt][1], sacc[nt][2], sacc[nt][3],
                        qa[2 * kcp][0], qa[2 * kcp][1], qa[2 * kcp][2], qa[2 * kcp][3],
                        u(f.x), u(f.y));
                mma_f16(sacc[nt][0], sacc[nt][1], sacc[nt][2], sacc[nt][3],
                        qa[2 * kcp + 1][0], qa[2 * kcp + 1][1], qa[2 * kcp + 1][2], qa[2 * kcp + 1][3],
                        u(f.z), u(f.w));
            }
        }

        // store prefetched K into next stage
        if (kt < 31) {
#pragma unroll
            for (int i = 0; i < 8; ++i) {
                int r = sK + 8 * i;
                int xr = (r & 7) << 2;
                KsN[r * 32 + (kx0 ^ xr)] = pack2(pk[i].x, pk[i].y);
                KsN[r * 32 + (kx1 ^ xr)] = pack2(pk[i].z, pk[i].w);
            }
        }

        // prefetch next V tile (regs live across softmax + PV)
        float4 pva[4], pvb[4];
        if (kt < 31) {
#pragma unroll
            for (int j = 0; j < 4; ++j) {
                pva[j] = *reinterpret_cast<const float4*>(Vt + (size_t)(2 * rp    ) * 64 + 16 * w + 4 * j);
                pvb[j] = *reinterpret_cast<const float4*>(Vt + (size_t)(2 * rp + 1) * 64 + 16 * w + 4 * j);
            }
        }

        // logits: t = S*scale*log2e + log2(gate)
#pragma unroll
        for (int nt = 0; nt < 8; ++nt) {
            sacc[nt][0] = sacc[nt][0] * SL2 + gA[nt].x;
            sacc[nt][1] = sacc[nt][1] * SL2 + gA[nt].y;
            sacc[nt][2] = sacc[nt][2] * SL2 + gB[nt].x;
            sacc[nt][3] = sacc[nt][3] * SL2 + gB[nt].y;
        }

        // online softmax
        float mn0 = m0, mn1 = m1;
#pragma unroll
        for (int nt = 0; nt < 8; ++nt) {
            mn0 = fmaxf(mn0, fmaxf(sacc[nt][0], sacc[nt][1]));
            mn1 = fmaxf(mn1, fmaxf(sacc[nt][2], sacc[nt][3]));
        }
        mn0 = fmaxf(mn0, __shfl_xor_sync(0xffffffffu, mn0, 1));
        mn0 = fmaxf(mn0, __shfl_xor_sync(0xffffffffu, mn0, 2));
        mn1 = fmaxf(mn1, __shfl_xor_sync(0xffffffffu, mn1, 1));
        mn1 = fmaxf(mn1, __shfl_xor_sync(0xffffffffu, mn1, 2));
        float al0 = exp2f(m0 - mn0), al1 = exp2f(m1 - mn1);
        m0 = mn0; m1 = mn1;
        l0 *= al0; l1 *= al1;
#pragma unroll
        for (int ot = 0; ot < 8; ++ot) {
            accO[ot][0] *= al0; accO[ot][1] *= al0;
            accO[ot][2] *= al1; accO[ot][3] *= al1;
        }

        // P = exp2(t - m); accumulate l; overwrite sacc with P (f32)
#pragma unroll
        for (int nt = 0; nt < 8; ++nt) {
            sacc[nt][0] = exp2f(sacc[nt][0] - m0);
            sacc[nt][1] = exp2f(sacc[nt][1] - m0);
            sacc[nt][2] = exp2f(sacc[nt][2] - m1);
            sacc[nt][3] = exp2f(sacc[nt][3] - m1);
            l0 += sacc[nt][0] + sacc[nt][1];
            l1 += sacc[nt][2] + sacc[nt][3];
        }

        // ---- O += P@V : 2 ktp x 8 ot; P A-frags = packed C-frags ----
#pragma unroll
        for (int ktp = 0; ktp < 2; ++ktp) {
            // knt even = 2*ktp (sacc[4ktp], sacc[4ktp+1]); knt odd (sacc[4ktp+2], sacc[4ktp+3])
            unsigned aE0 = pack2(sacc[4 * ktp][0],     sacc[4 * ktp][1]);
            unsigned aE1 = pack2(sacc[4 * ktp][2],     sacc[4 * ktp][3]);
            unsigned aE2 = pack2(sacc[4 * ktp + 1][0], sacc[4 * ktp + 1][1]);
            unsigned aE3 = pack2(sacc[4 * ktp + 1][2], sacc[4 * ktp + 1][3]);
            unsigned aO0 = pack2(sacc[4 * ktp + 2][0], sacc[4 * ktp + 2][1]);
            unsigned aO1 = pack2(sacc[4 * ktp + 2][2], sacc[4 * ktp + 2][3]);
            unsigned aO2 = pack2(sacc[4 * ktp + 3][0], sacc[4 * ktp + 3][1]);
            unsigned aO3 = pack2(sacc[4 * ktp + 3][2], sacc[4 * ktp + 3][3]);
            int F = 2 * tg + ktp;
#pragma unroll
            for (int ot = 0; ot < 8; ++ot) {
                int d = ot * 8 + g;
                float4 f = *reinterpret_cast<const float4*>(Vs + d * 32 + ((F ^ g) << 2));
                mma_f16(accO[ot][0], accO[ot][1], accO[ot][2], accO[ot][3],
                        aE0, aE1, aE2, aE3, u(f.x), u(f.y));
                mma_f16(accO[ot][0], accO[ot][1], accO[ot][2], accO[ot][3],
                        aO0, aO1, aO2, aO3, u(f.z), u(f.w));
            }
        }

        // store prefetched V into next stage
        if (kt < 31) {
#pragma unroll
            for (int j = 0; j < 4; ++j) {
                int d = 16 * w + 4 * j;
                VsN[(d    ) * 32 + (vx ^ (((d    ) & 7) << 2))] = pack2(pva[j].x, pvb[j].x);
                VsN[(d + 1) * 32 + (vx ^ (((d + 1) & 7) << 2))] = pack2(pva[j].y, pvb[j].y);
                VsN[(d + 2) * 32 + (vx ^ (((d + 2) & 7) << 2))] = pack2(pva[j].z, pvb[j].z);
                VsN[(d + 3) * 32 + (vx ^ (((d + 3) & 7) << 2))] = pack2(pva[j].w, pvb[j].w);
            }
        }
        __syncthreads();
    }

    // quad-reduce the softmax denominators
    l0 += __shfl_xor_sync(0xffffffffu, l0, 1);
    l0 += __shfl_xor_sync(0xffffffffu, l0, 2);
    l1 += __shfl_xor_sync(0xffffffffu, l1, 1);
    l1 += __shfl_xor_sync(0xffffffffu, l1, 2);

    float inv0 = 1.0f / l0, inv1 = 1.0f / l1;
    int qr0 = q0 + w * 16 + g, qr1 = qr0 + 8;
    float* O0 = g_AO + ((size_t)(bz * Nn + qr0)) * DM + h * 64;
    float* O1 = g_AO + ((size_t)(bz * Nn + qr1)) * DM + h * 64;
#pragma unroll
    for (int ot = 0; ot < 8; ++ot) {
        int d = ot * 8 + 2 * tg;
        *reinterpret_cast<float2*>(O0 + d) = make_float2(accO[ot][0] * inv0, accO[ot][1] * inv0);
        *reinterpret_cast<float2*>(O1 + d) = make_float2(accO[ot][2] * inv1, accO[ot][3] * inv1);
    }
}

// ============================================================
extern "C" void kernel_launch(void* const* d_in, const int* in_sizes, int n_in,
                              void* d_out, int out_size) {
    const float* Qin  = (const float*)d_in[0];
    const float* KVin = (const float*)d_in[1];
    const float* SC   = (const float*)d_in[2];
    const float* Wq   = (const float*)d_in[3];
    const float* Wqb  = (const float*)d_in[4];
    const float* Wk   = (const float*)d_in[5];
    const float* Wkb  = (const float*)d_in[6];
    const float* Wv   = (const float*)d_in[7];
    const float* Wvb  = (const float*)d_in[8];
    const float* gw   = (const float*)d_in[9];
    const float* gb   = (const float*)d_in[10];
    const float* Wo   = (const float*)d_in[11];
    const float* Wob  = (const float*)d_in[12];
    float* out = (float*)d_out;

    cudaFuncSetAttribute(gemm512,      cudaFuncAttributeMaxDynamicSharedMemorySize, GEMM_SMEM);
    cudaFuncSetAttribute(flash_kernel, cudaFuncAttributeMaxDynamicSharedMemorySize, FLASH_SMEM);

    gate_kernel<<<16384, 256>>>(reinterpret_cast<const float4*>(SC), gw, gb);

    gemm512<<<dim3(8, 64),  256, GEMM_SMEM>>>(Qin,  Wq, Wqb, nullptr, nullptr, nullptr, 0, 0);
    gemm512<<<dim3(16, 64), 256, GEMM_SMEM>>>(KVin, Wk, Wkb, Wv,      Wvb,     nullptr, 0, 4);

    flash_kernel<<<dim3(8, 32, 4), 128, FLASH_SMEM>>>();

    gemm512<<<dim3(8, 64),  256, GEMM_SMEM>>>(nullptr, Wo, Wob, nullptr, nullptr, out, 1, 3);
}

// round 11
// speedup vs baseline: 1.8552x; 1.8552x over previous
#include <cuda_runtime.h>
#include <cuda_fp16.h>
#include <cstdint>

#define Bb   4
#define Nn   2048
#define DM   512
#define Hh   8
#define DH   64
#define SCALE_F 0.125f
#define LOG2E 1.4426950408889634f

#define GEMM_SMEM  (2 * 6912 * 4)   // 55296 B
#define FLASH_SMEM 32768            // 2 stages x (K 8KB + V 8KB), fp16

// ---- scratch (static __device__, allocation-free) ----
__device__ float g_G [(size_t)Bb * Nn * Nn];
__device__ float g_Q [(size_t)Bb * Hh * Nn * DH];
__device__ float g_K [(size_t)Bb * Hh * Nn * DH];
__device__ float g_V [(size_t)Bb * Hh * Nn * DH];
__device__ float g_AO[(size_t)Bb * Nn * DM];

// ---- helpers ----
__device__ __forceinline__ unsigned f2tf(float x) {
    unsigned r;
    asm("cvt.rna.tf32.f32 %0, %1;" : "=r"(r) : "f"(x));
    return r;
}
__device__ __forceinline__ float f2tff(float x) { return __uint_as_float(f2tf(x)); }
__device__ __forceinline__ unsigned u(float x) { return __float_as_uint(x); }
__device__ __forceinline__ unsigned pack2(float lo, float hi) {
    __half2 h = __floats2half2_rn(lo, hi);
    return *reinterpret_cast<unsigned*>(&h);
}

__device__ __forceinline__ void mma_tf32(float& d0, float& d1, float& d2, float& d3,
                                         unsigned a0, unsigned a1, unsigned a2, unsigned a3,
                                         unsigned b0, unsigned b1) {
    asm volatile(
        "mma.sync.aligned.m16n8k8.row.col.f32.tf32.tf32.f32 "
        "{%0,%1,%2,%3}, {%4,%5,%6,%7}, {%8,%9}, {%0,%1,%2,%3};"
        : "+f"(d0), "+f"(d1), "+f"(d2), "+f"(d3)
        : "r"(a0), "r"(a1), "r"(a2), "r"(a3), "r"(b0), "r"(b1));
}

__device__ __forceinline__ void mma_f16(float& d0, float& d1, float& d2, float& d3,
                                        unsigned a0, unsigned a1, unsigned a2, unsigned a3,
                                        unsigned b0, unsigned b1) {
    asm volatile(
        "mma.sync.aligned.m16n8k16.row.col.f32.f16.f16.f32 "
        "{%0,%1,%2,%3}, {%4,%5,%6,%7}, {%8,%9}, {%0,%1,%2,%3};"
        : "+f"(d0), "+f"(d1), "+f"(d2), "+f"(d3)
        : "r"(a0), "r"(a1), "r"(a2), "r"(a3), "r"(b0), "r"(b1));
}

__device__ __forceinline__ void ldsm4t(unsigned& r0, unsigned& r1, unsigned& r2, unsigned& r3,
                                       unsigned addr) {
    asm volatile("ldmatrix.sync.aligned.m8n8.x4.trans.shared.b16 {%0,%1,%2,%3}, [%4];"
                 : "=r"(r0), "=r"(r1), "=r"(r2), "=r"(r3) : "r"(addr));
}

// ============================================================
// Kernel 0: gate precompute  G = log2(sigmoid(w*SC + b) + 1e-8)
// ============================================================
__global__ void gate_kernel(const float4* __restrict__ SC,
                            const float* __restrict__ gw,
                            const float* __restrict__ gb) {
    int i = blockIdx.x * 256 + threadIdx.x;
    float w = __ldg(gw), b = __ldg(gb);
    float4 s = SC[i];
    float4 r;
    r.x = __log2f(__fdividef(1.f, 1.f + __expf(-(s.x * w + b))) + 1e-8f);
    r.y = __log2f(__fdividef(1.f, 1.f + __expf(-(s.y * w + b))) + 1e-8f);
    r.z = __log2f(__fdividef(1.f, 1.f + __expf(-(s.z * w + b))) + 1e-8f);
    r.w = __log2f(__fdividef(1.f, 1.f + __expf(-(s.w * w + b))) + 1e-8f);
    reinterpret_cast<float4*>(g_G)[i] = r;
}

// ============================================================
// Kernel 1: tf32 GEMM (unchanged from R8)
// ============================================================
__global__ __launch_bounds__(256) void gemm512(const float* __restrict__ Aext,
                                               const float* __restrict__ Wa,
                                               const float* __restrict__ biasa,
                                               const float* __restrict__ Wb,
                                               const float* __restrict__ biasb,
                                               float* __restrict__ Cext,
                                               int amode, int cmode) {
    extern __shared__ float dyn[];

    const float* A = amode ? g_AO : Aext;
    const float* W    = Wa;
    const float* bias = biasa;
    float* C;
    if      (cmode == 0) C = g_Q;
    else if (cmode == 3) C = Cext;
    else {
        if (blockIdx.x >= 8) { W = Wb; bias = biasb; C = g_V; }
        else                 {                        C = g_K; }
    }
    const bool scatter = (cmode != 3);

    int tid  = threadIdx.x;
    int warp = tid >> 5, lane = tid & 31;
    int g = lane >> 2, tg = lane & 3;
    int wm = warp >> 1, wn = warp & 1;
    int mbase = blockIdx.y * 128, nbase = (blockIdx.x & 7) * 64;

    int ar = tid >> 3, acc_ = (tid & 7) * 4;
    int ap = ar * 36 + (acc_ >> 2);
    int br = tid >> 3;
    int bp = br * 36 + (acc_ >> 2);

    float acc[2][4][4];
#pragma unroll
    for (int mt = 0; mt < 2; ++mt)
#pragma unroll
        for (int nt = 0; nt < 4; ++nt)
#pragma unroll
            for (int i = 0; i < 4; ++i) acc[mt][nt][i] = 0.f;

    {
        float* As = dyn;
        float* Bs = dyn + 4608;
#pragma unroll
        for (int i = 0; i < 4; ++i) {
            float4 v = *reinterpret_cast<const float4*>(A + (size_t)(mbase + ar + i * 32) * 512 + acc_);
            int p = ap + i * 32 * 36;
            As[p] = f2tff(v.x); As[p + 8] = f2tff(v.y); As[p + 16] = f2tff(v.z); As[p + 24] = f2tff(v.w);
        }
#pragma unroll
        for (int i = 0; i < 2; ++i) {
            float4 v = *reinterpret_cast<const float4*>(W + (size_t)(nbase + br + i * 32) * 512 + acc_);
            int p = bp + i * 32 * 36;
            Bs[p] = f2tff(v.x); Bs[p + 8] = f2tff(v.y); Bs[p + 16] = f2tff(v.z); Bs[p + 24] = f2tff(v.w);
        }
    }
    __syncthreads();

    for (int kt = 0; kt < 16; ++kt) {
        float* As = dyn + (kt & 1) * 6912;
        float* Bs = As + 4608;
        float* AsN = dyn + ((kt + 1) & 1) * 6912;
        float* BsN = AsN + 4608;

        float4 pa[4], pb[2];
        if (kt < 15) {
            int k0 = (kt + 1) * 32;
#pragma unroll
            for (int i = 0; i < 4; ++i)
                pa[i] = *reinterpret_cast<const float4*>(A + (size_t)(mbase + ar + i * 32) * 512 + k0 + acc_);
#pragma unroll
            for (int i = 0; i < 2; ++i)
                pb[i] = *reinterpret_cast<const float4*>(W + (size_t)(nbase + br + i * 32) * 512 + k0 + acc_);
        }

        unsigned a[2][4][4];
#pragma unroll
        for (int mt = 0; mt < 2; ++mt) {
            const float4* p0 = reinterpret_cast<const float4*>(As + (wm * 32 + mt * 16 + g    ) * 36 + tg * 8);
            const float4* p1 = reinterpret_cast<const float4*>(As + (wm * 32 + mt * 16 + g + 8) * 36 + tg * 8);
            float4 f0 = p0[0], f1 = p0[1];
            float4 f2 = p1[0], f3 = p1[1];
            a[mt][0][0] = u(f0.x); a[mt][0][1] = u(f2.x); a[mt][0][2] = u(f0.y); a[mt][0][3] = u(f2.y);
            a[mt][1][0] = u(f0.z); a[mt][1][1] = u(f2.z); a[mt][1][2] = u(f0.w); a[mt][1][3] = u(f2.w);
            a[mt][2][0] = u(f1.x); a[mt][2][1] = u(f3.x); a[mt][2][2] = u(f1.y); a[mt][2][3] = u(f3.y);
            a[mt][3][0] = u(f1.z); a[mt][3][1] = u(f3.z); a[mt][3][2] = u(f1.w); a[mt][3][3] = u(f3.w);
        }

#pragma unroll
        for (int kcp = 0; kcp < 2; ++kcp) {
            int kc0 = kcp * 2, kc1 = kcp * 2 + 1;
#pragma unroll
            for (int nt = 0; nt < 4; ++nt) {
                float4 f = reinterpret_cast<const float4*>(Bs + (wn * 32 + nt * 8 + g) * 36 + tg * 8)[kcp];
                mma_tf32(acc[0][nt][0], acc[0][nt][1], acc[0][nt][2], acc[0][nt][3],
                         a[0][kc0][0], a[0][kc0][1], a[0][kc0][2], a[0][kc0][3], u(f.x), u(f.y));
                mma_tf32(acc[1][nt][0], acc[1][nt][1], acc[1][nt][2], acc[1][nt][3],
                         a[1][kc0][0], a[1][kc0][1], a[1][kc0][2], a[1][kc0][3], u(f.x), u(f.y));
                mma_tf32(acc[0][nt][0], acc[0][nt][1], acc[0][nt][2], acc[0][nt][3],
                         a[0][kc1][0], a[0][kc1][1], a[0][kc1][2], a[0][kc1][3], u(f.z), u(f.w));
                mma_tf32(acc[1][nt][0], acc[1][nt][1], acc[1][nt][2], acc[1][nt][3],
                         a[1][kc1][0], a[1][kc1][1], a[1][kc1][2], a[1][kc1][3], u(f.z), u(f.w));
            }
        }

        if (kt < 15) {
#pragma unroll
            for (int i = 0; i < 4; ++i) {
                int p = ap + i * 32 * 36;
                AsN[p] = f2tff(pa[i].x); AsN[p + 8] = f2tff(pa[i].y);
                AsN[p + 16] = f2tff(pa[i].z); AsN[p + 24] = f2tff(pa[i].w);
            }
#pragma unroll
            for (int i = 0; i < 2; ++i) {
                int p = bp + i * 32 * 36;
                BsN[p] = f2tff(pb[i].x); BsN[p + 8] = f2tff(pb[i].y);
                BsN[p + 16] = f2tff(pb[i].z); BsN[p + 24] = f2tff(pb[i].w);
            }
        }
        __syncthreads();
    }

#pragma unroll
    for (int mt = 0; mt < 2; ++mt)
#pragma unroll
        for (int nt = 0; nt < 4; ++nt) {
            int col = nbase + wn * 32 + nt * 8 + 2 * tg;
            float b0 = bias[col], b1 = bias[col + 1];
            int r0 = mbase + wm * 32 + mt * 16 + g;
            int r1 = r0 + 8;
            float v00 = acc[mt][nt][0] + b0, v01 = acc[mt][nt][1] + b1;
            float v10 = acc[mt][nt][2] + b0, v11 = acc[mt][nt][3] + b1;
            if (scatter) {
                int h = col >> 6, d = col & 63;
                {
                    int b = r0 >> 11, n = r0 & 2047;
                    float* p = C + (size_t)(((b << 3) + h) * 2048 + n) * 64 + d;
                    *reinterpret_cast<float2*>(p) = make_float2(v00, v01);
                }
                {
                    int b = r1 >> 11, n = r1 & 2047;
                    float* p = C + (size_t)(((b << 3) + h) * 2048 + n) * 64 + d;
                    *reinterpret_cast<float2*>(p) = make_float2(v10, v11);
                }
            } else {
                *reinterpret_cast<float2*>(C + (size_t)r0 * 512 + col) = make_float2(v00, v01);
                *reinterpret_cast<float2*>(C + (size_t)r1 * 512 + col) = make_float2(v10, v11);
            }
        }
}

// ============================================================
// Kernel 2: fp16 flash attention (m16n8k16), BM=64, BN=64,
//  128 threads, double-buffered.  Per stage (b32 units):
//   K (2048): 64 rows x 32, pair p of row r at col ((p&3)*8+(p>>2)) ^ swz
//   V (2048): 64 rows x 32 fp16 row-major, 16B-chunk c of row r at c^(r&7)
//  K fragments: LDS.128.  V fragments: ldmatrix.x4.trans (PTX B-layout).
//  Both K and V global loads are coalesced (half-warp per row).
// ============================================================
__global__ __launch_bounds__(128, 2) void flash_kernel() {
    extern __shared__ float smf[];
    unsigned* smU = reinterpret_cast<unsigned*>(smf);
    unsigned smb;
    asm("{ .reg .u64 t; cvta.to.shared.u64 t, %1; cvt.u32.u64 %0, t; }"
        : "=r"(smb) : "l"(smf));

    int tid = threadIdx.x, w = tid >> 5, lane = tid & 31;
    int g = lane >> 2, tg = lane & 3;
    int h = blockIdx.x, qt = blockIdx.y, bz = blockIdx.z;
    int bh = bz * 8 + h;
    const float* Qb = g_Q + (size_t)bh * Nn * DH;
    const float* Kb = g_K + (size_t)bh * Nn * DH;
    const float* Vb = g_V + (size_t)bh * Nn * DH;
    int q0 = qt * 64;

    // ---- coalesced staging map (K and V identical): half-warp per row ----
    int sK  = ((w >> 1) << 2) + (w & 1) + ((lane >> 4) << 1);   // rows sK+8i
    int m   = lane & 15;
    int scc = m * 4;                                            // float col
    int p0  = 2 * m;
    int kx0 = ((p0 & 3) << 3) + (p0 >> 2);
    int kx1 = (((p0 + 1) & 3) << 3) + ((p0 + 1) >> 2);
    // V STS (b32): row r, b32 cols 2m,2m+1 -> chunk m>>1, swizzle ^(r&7)
    int vch = m >> 1, vin = 2 * (m & 1);
    // V LDSM lane constants
    int matq = lane >> 3, ii = lane & 7;
    int vrowb = (((matq & 1) << 3) + ii) * 128;    // byte offset of row within 16-row block
    int chh = matq >> 1;

    // ---- stage Q tile [64,64] fp32 (stride 68) and read fp16 fragments ----
#pragma unroll
    for (int i = 0; i < 8; ++i) {
        int idx = tid + i * 128;
        int r = idx >> 4, c = (idx & 15) * 4;
        float4 v = *reinterpret_cast<const float4*>(Qb + (size_t)(q0 + r) * 64 + c);
        *reinterpret_cast<float4*>(smf + r * 68 + c) = v;
    }
    __syncthreads();
    unsigned qa[4][4];
    {
        int r0 = w * 16 + g, r1 = r0 + 8;
#pragma unroll
        for (int kc = 0; kc < 4; ++kc) {
            float2 v0 = *reinterpret_cast<const float2*>(smf + r0 * 68 + kc * 16 + 2 * tg);
            float2 v1 = *reinterpret_cast<const float2*>(smf + r1 * 68 + kc * 16 + 2 * tg);
            float2 v2 = *reinterpret_cast<const float2*>(smf + r0 * 68 + kc * 16 + 2 * tg + 8);
            float2 v3 = *reinterpret_cast<const float2*>(smf + r1 * 68 + kc * 16 + 2 * tg + 8);
            qa[kc][0] = pack2(v0.x, v0.y);
            qa[kc][1] = pack2(v1.x, v1.y);
            qa[kc][2] = pack2(v2.x, v2.y);
            qa[kc][3] = pack2(v3.x, v3.y);
        }
    }
    __syncthreads();

    // ---- stage K/V kt=0 into stage 0 (both coalesced) ----
    {
        unsigned* K0 = smU;
        unsigned* V0 = smU + 2048;
#pragma unroll
        for (int i = 0; i < 8; ++i) {
            int r = sK + 8 * i;
            float4 v = *reinterpret_cast<const float4*>(Kb + (size_t)r * 64 + scc);
            int xr = (r & 7) << 2;
            K0[r * 32 + (kx0 ^ xr)] = pack2(v.x, v.y);
            K0[r * 32 + (kx1 ^ xr)] = pack2(v.z, v.w);
            float4 vv = *reinterpret_cast<const float4*>(Vb + (size_t)r * 64 + scc);
            int vi = r * 32 + (((vch) ^ (r & 7)) << 2) + vin;
            uint2 val; val.x = pack2(vv.x, vv.y); val.y = pack2(vv.z, vv.w);
            *reinterpret_cast<uint2*>(&V0[vi]) = val;
        }
    }
    __syncthreads();

    float accO[8][4];
#pragma unroll
    for (int ot = 0; ot < 8; ++ot)
#pragma unroll
        for (int i = 0; i < 4; ++i) accO[ot][i] = 0.f;
    float m0 = -1e30f, m1 = -1e30f, l0 = 0.f, l1 = 0.f;

    const float* G0 = g_G + ((size_t)bz * Nn + (q0 + w * 16 + g)) * Nn;
    const float* G1 = G0 + (size_t)8 * Nn;
    const float SL2 = SCALE_F * LOG2E;

    for (int kt = 0; kt < 32; ++kt) {
        unsigned* Ks = smU + (kt & 1) * 4096;
        unsigned* KsN = smU + ((kt + 1) & 1) * 4096;
        unsigned* VsN = KsN + 2048;
        unsigned vbase = smb + ((kt & 1) * 4096 + 2048) * 4;   // byte addr of Vs

        const float* Kt = Kb + (size_t)(kt + 1) * 4096;
        const float* Vt = Vb + (size_t)(kt + 1) * 4096;

        // prefetch next K tile (coalesced; regs live across QK only)
        float4 pk[8];
        if (kt < 31) {
#pragma unroll
            for (int i = 0; i < 8; ++i)
                pk[i] = *reinterpret_cast<const float4*>(Kt + (size_t)(sK + 8 * i) * 64 + scc);
        }

        // prefetch gate rows (consumed after QK)
        float2 gA[8], gB[8];
        {
            int cbase = kt * 64 + 2 * tg;
#pragma unroll
            for (int nt = 0; nt < 8; ++nt) {
                gA[nt] = *reinterpret_cast<const float2*>(G0 + cbase + nt * 8);
                gB[nt] = *reinterpret_cast<const float2*>(G1 + cbase + nt * 8);
            }
        }

        // ---- S = Q K^T : 2 kc-pairs x 8 nt, 8 independent chains ----
        float sacc[8][4];
#pragma unroll
        for (int nt = 0; nt < 8; ++nt)
#pragma unroll
            for (int i = 0; i < 4; ++i) sacc[nt][i] = 0.f;
#pragma unroll
        for (int kcp = 0; kcp < 2; ++kcp) {
            int F = 2 * tg + kcp;
#pragma unroll
            for (int nt = 0; nt < 8; ++nt) {
                int r = nt * 8 + g;
                float4 f = *reinterpret_cast<const float4*>(Ks + r * 32 + ((F ^ g) << 2));
                mma_f16(sacc[nt][0], sacc[nt][1], sacc[nt][2], sacc[nt][3],
                        qa[2 * kcp][0], qa[2 * kcp][1], qa[2 * kcp][2], qa[2 * kcp][3],
                        u(f.x), u(f.y));
                mma_f16(sacc[nt][0], sacc[nt][1], sacc[nt][2], sacc[nt][3],
                        qa[2 * kcp + 1][0], qa[2 * kcp + 1][1], qa[2 * kcp + 1][2], qa[2 * kcp + 1][3],
                        u(f.z), u(f.w));
            }
        }

        // store prefetched K into next stage
        if (kt < 31) {
#pragma unroll
            for (int i = 0; i < 8; ++i) {
                int r = sK + 8 * i;
                int xr = (r & 7) << 2;
                KsN[r * 32 + (kx0 ^ xr)] = pack2(pk[i].x, pk[i].y);
                KsN[r * 32 + (kx1 ^ xr)] = pack2(pk[i].z, pk[i].w);
            }
        }

        // prefetch next V tile (COALESCED — same mapping as K)
        float4 pv[8];
        if (kt < 31) {
#pragma unroll
            for (int i = 0; i < 8; ++i)
                pv[i] = *reinterpret_cast<const float4*>(Vt + (size_t)(sK + 8 * i) * 64 + scc);
        }

        // logits: t = S*scale*log2e + log2(gate)
#pragma unroll
        for (int nt = 0; nt < 8; ++nt) {
            sacc[nt][0] = sacc[nt][0] * SL2 + gA[nt].x;
            sacc[nt][1] = sacc[nt][1] * SL2 + gA[nt].y;
            sacc[nt][2] = sacc[nt][2] * SL2 + gB[nt].x;
            sacc[nt][3] = sacc[nt][3] * SL2 + gB[nt].y;
        }

        // online softmax
        float mn0 = m0, mn1 = m1;
#pragma unroll
        for (int nt = 0; nt < 8; ++nt) {
            mn0 = fmaxf(mn0, fmaxf(sacc[nt][0], sacc[nt][1]));
            mn1 = fmaxf(mn1, fmaxf(sacc[nt][2], sacc[nt][3]));
        }
        mn0 = fmaxf(mn0, __shfl_xor_sync(0xffffffffu, mn0, 1));
        mn0 = fmaxf(mn0, __shfl_xor_sync(0xffffffffu, mn0, 2));
        mn1 = fmaxf(mn1, __shfl_xor_sync(0xffffffffu, mn1, 1));
        mn1 = fmaxf(mn1, __shfl_xor_sync(0xffffffffu, mn1, 2));
        float al0 = exp2f(m0 - mn0), al1 = exp2f(m1 - mn1);
        m0 = mn0; m1 = mn1;
        l0 *= al0; l1 *= al1;
#pragma unroll
        for (int ot = 0; ot < 8; ++ot) {
            accO[ot][0] *= al0; accO[ot][1] *= al0;
            accO[ot][2] *= al1; accO[ot][3] *= al1;
        }

        // P = exp2(t - m); accumulate l
#pragma unroll
        for (int nt = 0; nt < 8; ++nt) {
            sacc[nt][0] = exp2f(sacc[nt][0] - m0);
            sacc[nt][1] = exp2f(sacc[nt][1] - m0);
            sacc[nt][2] = exp2f(sacc[nt][2] - m1);
            sacc[nt][3] = exp2f(sacc[nt][3] - m1);
            l0 += sacc[nt][0] + sacc[nt][1];
            l1 += sacc[nt][2] + sacc[nt][3];
        }

        // ---- O += P@V : 4 k16-steps x 8 ot (B frags via ldmatrix.trans) ----
#pragma unroll
        for (int s = 0; s < 4; ++s) {
            unsigned aP0 = pack2(sacc[2 * s][0],     sacc[2 * s][1]);
            unsigned aP1 = pack2(sacc[2 * s][2],     sacc[2 * s][3]);
            unsigned aP2 = pack2(sacc[2 * s + 1][0], sacc[2 * s + 1][1]);
            unsigned aP3 = pack2(sacc[2 * s + 1][2], sacc[2 * s + 1][3]);
            unsigned base_s = vbase + s * 2048 + vrowb;
#pragma unroll
            for (int otp = 0; otp < 4; ++otp) {
                unsigned b0, b1, b2, b3;
                ldsm4t(b0, b1, b2, b3, base_s + ((((2 * otp + chh) ^ ii)) << 4));
                mma_f16(accO[2 * otp][0], accO[2 * otp][1], accO[2 * otp][2], accO[2 * otp][3],
                        aP0, aP1, aP2, aP3, b0, b1);
                mma_f16(accO[2 * otp + 1][0], accO[2 * otp + 1][1], accO[2 * otp + 1][2], accO[2 * otp + 1][3],
                        aP0, aP1, aP2, aP3, b2, b3);
            }
        }

        // store prefetched V into next stage (row-major fp16, chunk-swizzled)
        if (kt < 31) {
#pragma unroll
            for (int i = 0; i < 8; ++i) {
                int r = sK + 8 * i;
                int vi = r * 32 + ((vch ^ (r & 7)) << 2) + vin;
                uint2 val; val.x = pack2(pv[i].x, pv[i].y); val.y = pack2(pv[i].z, pv[i].w);
                *reinterpret_cast<uint2*>(&VsN[vi]) = val;
            }
        }
        __syncthreads();
    }

    // quad-reduce the softmax denominators
    l0 += __shfl_xor_sync(0xffffffffu, l0, 1);
    l0 += __shfl_xor_sync(0xffffffffu, l0, 2);
    l1 += __shfl_xor_sync(0xffffffffu, l1, 1);
    l1 += __shfl_xor_sync(0xffffffffu, l1, 2);

    float inv0 = 1.0f / l0, inv1 = 1.0f / l1;
    int qr0 = q0 + w * 16 + g, qr1 = qr0 + 8;
    float* O0 = g_AO + ((size_t)(bz * Nn + qr0)) * DM + h * 64;
    float* O1 = g_AO + ((size_t)(bz * Nn + qr1)) * DM + h * 64;
#pragma unroll
    for (int ot = 0; ot < 8; ++ot) {
        int d = ot * 8 + 2 * tg;
        *reinterpret_cast<float2*>(O0 + d) = make_float2(accO[ot][0] * inv0, accO[ot][1] * inv0);
        *reinterpret_cast<float2*>(O1 + d) = make_float2(accO[ot][2] * inv1, accO[ot][3] * inv1);
    }
}

// ============================================================
extern "C" void kernel_launch(void* const* d_in, const int* in_sizes, int n_in,
                              void* d_out, int out_size) {
    const float* Qin  = (const float*)d_in[0];
    const float* KVin = (const float*)d_in[1];
    const float* SC   = (const float*)d_in[2];
    const float* Wq   = (const float*)d_in[3];
    const float* Wqb  = (const float*)d_in[4];
    const float* Wk   = (const float*)d_in[5];
    const float* Wkb  = (const float*)d_in[6];
    const float* Wv   = (const float*)d_in[7];
    const float* Wvb  = (const float*)d_in[8];
    const float* gw   = (const float*)d_in[9];
    const float* gb   = (const float*)d_in[10];
    const float* Wo   = (const float*)d_in[11];
    const float* Wob  = (const float*)d_in[12];
    float* out = (float*)d_out;

    cudaFuncSetAttribute(gemm512,      cudaFuncAttributeMaxDynamicSharedMemorySize, GEMM_SMEM);
    cudaFuncSetAttribute(flash_kernel, cudaFuncAttributeMaxDynamicSharedMemorySize, FLASH_SMEM);

    gate_kernel<<<16384, 256>>>(reinterpret_cast<const float4*>(SC), gw, gb);

    gemm512<<<dim3(8, 64),  256, GEMM_SMEM>>>(Qin,  Wq, Wqb, nullptr, nullptr, nullptr, 0, 0);
    gemm512<<<dim3(16, 64), 256, GEMM_SMEM>>>(KVin, Wk, Wkb, Wv,      Wvb,     nullptr, 0, 4);

    flash_kernel<<<dim3(8, 32, 4), 128, FLASH_SMEM>>>();

    gemm512<<<dim3(8, 64),  256, GEMM_SMEM>>>(nullptr, Wo, Wob, nullptr, nullptr, out, 1, 3);
}

// round 12
// speedup vs baseline: 2.2198x; 1.1965x over previous
#include <cuda_runtime.h>
#include <cuda_fp16.h>
#include <cstdint>

#define Bb   4
#define Nn   2048
#define DM   512
#define Hh   8
#define DH   64
#define SCALE_F 0.125f
#define LOG2E 1.4426950408889634f

#define GEMM_SMEM  (2 * 6912 * 4)   // 55296 B
#define FLASH_SMEM 32768            // 2 stages x (K 8KB + V 8KB), fp16

// ---- scratch (static __device__, allocation-free) ----
__device__ float  g_G [(size_t)Bb * Nn * Nn];
__device__ float  g_Q [(size_t)Bb * Hh * Nn * DH];
__device__ __half g_K [(size_t)Bb * Hh * Nn * DH];   // fp16, written by proj gemm
__device__ __half g_V [(size_t)Bb * Hh * Nn * DH];   // fp16
__device__ float  g_AO[(size_t)Bb * Nn * DM];

// ---- helpers ----
__device__ __forceinline__ unsigned f2tf(float x) {
    unsigned r;
    asm("cvt.rna.tf32.f32 %0, %1;" : "=r"(r) : "f"(x));
    return r;
}
__device__ __forceinline__ float f2tff(float x) { return __uint_as_float(f2tf(x)); }
__device__ __forceinline__ unsigned u(float x) { return __float_as_uint(x); }
__device__ __forceinline__ unsigned pack2(float lo, float hi) {
    __half2 h = __floats2half2_rn(lo, hi);
    return *reinterpret_cast<unsigned*>(&h);
}

#define CP16(dst, src) \
    asm volatile("cp.async.cg.shared.global [%0], [%1], 16;" :: "r"(dst), "l"(src))

__device__ __forceinline__ void mma_tf32(float& d0, float& d1, float& d2, float& d3,
                                         unsigned a0, unsigned a1, unsigned a2, unsigned a3,
                                         unsigned b0, unsigned b1) {
    asm volatile(
        "mma.sync.aligned.m16n8k8.row.col.f32.tf32.tf32.f32 "
        "{%0,%1,%2,%3}, {%4,%5,%6,%7}, {%8,%9}, {%0,%1,%2,%3};"
        : "+f"(d0), "+f"(d1), "+f"(d2), "+f"(d3)
        : "r"(a0), "r"(a1), "r"(a2), "r"(a3), "r"(b0), "r"(b1));
}

__device__ __forceinline__ void mma_f16(float& d0, float& d1, float& d2, float& d3,
                                        unsigned a0, unsigned a1, unsigned a2, unsigned a3,
                                        unsigned b0, unsigned b1) {
    asm volatile(
        "mma.sync.aligned.m16n8k16.row.col.f32.f16.f16.f32 "
        "{%0,%1,%2,%3}, {%4,%5,%6,%7}, {%8,%9}, {%0,%1,%2,%3};"
        : "+f"(d0), "+f"(d1), "+f"(d2), "+f"(d3)
        : "r"(a0), "r"(a1), "r"(a2), "r"(a3), "r"(b0), "r"(b1));
}

__device__ __forceinline__ void ldsm4(unsigned& r0, unsigned& r1, unsigned& r2, unsigned& r3,
                                      unsigned addr) {
    asm volatile("ldmatrix.sync.aligned.m8n8.x4.shared.b16 {%0,%1,%2,%3}, [%4];"
                 : "=r"(r0), "=r"(r1), "=r"(r2), "=r"(r3) : "r"(addr));
}
__device__ __forceinline__ void ldsm4t(unsigned& r0, unsigned& r1, unsigned& r2, unsigned& r3,
                                       unsigned addr) {
    asm volatile("ldmatrix.sync.aligned.m8n8.x4.trans.shared.b16 {%0,%1,%2,%3}, [%4];"
                 : "=r"(r0), "=r"(r1), "=r"(r2), "=r"(r3) : "r"(addr));
}

// ============================================================
// Kernel 0: gate precompute  G = log2(sigmoid(w*SC + b) + 1e-8)
// ============================================================
__global__ void gate_kernel(const float4* __restrict__ SC,
                            const float* __restrict__ gw,
                            const float* __restrict__ gb) {
    int i = blockIdx.x * 256 + threadIdx.x;
    float w = __ldg(gw), b = __ldg(gb);
    float4 s = SC[i];
    float4 r;
    r.x = __log2f(__fdividef(1.f, 1.f + __expf(-(s.x * w + b))) + 1e-8f);
    r.y = __log2f(__fdividef(1.f, 1.f + __expf(-(s.y * w + b))) + 1e-8f);
    r.z = __log2f(__fdividef(1.f, 1.f + __expf(-(s.z * w + b))) + 1e-8f);
    r.w = __log2f(__fdividef(1.f, 1.f + __expf(-(s.w * w + b))) + 1e-8f);
    reinterpret_cast<float4*>(g_G)[i] = r;
}

// ============================================================
// Kernel 1: tf32 GEMM (R8 core).  cmode: 0 -> g_Q(f32 scatter),
//  3 -> Cext row-major f32, 4 -> fused K|V scatter as FP16.
// ============================================================
__global__ __launch_bounds__(256) void gemm512(const float* __restrict__ Aext,
                                               const float* __restrict__ Wa,
                                               const float* __restrict__ biasa,
                                               const float* __restrict__ Wb,
                                               const float* __restrict__ biasb,
                                               float* __restrict__ Cext,
                                               int amode, int cmode) {
    extern __shared__ float dyn[];

    const float* A = amode ? g_AO : Aext;
    const float* W    = Wa;
    const float* bias = biasa;
    if (cmode == 4 && blockIdx.x >= 8) { W = Wb; bias = biasb; }

    int tid  = threadIdx.x;
    int warp = tid >> 5, lane = tid & 31;
    int g = lane >> 2, tg = lane & 3;
    int wm = warp >> 1, wn = warp & 1;
    int mbase = blockIdx.y * 128, nbase = (blockIdx.x & 7) * 64;

    int ar = tid >> 3, acc_ = (tid & 7) * 4;
    int ap = ar * 36 + (acc_ >> 2);
    int br = tid >> 3;
    int bp = br * 36 + (acc_ >> 2);

    float acc[2][4][4];
#pragma unroll
    for (int mt = 0; mt < 2; ++mt)
#pragma unroll
        for (int nt = 0; nt < 4; ++nt)
#pragma unroll
            for (int i = 0; i < 4; ++i) acc[mt][nt][i] = 0.f;

    {
        float* As = dyn;
        float* Bs = dyn + 4608;
#pragma unroll
        for (int i = 0; i < 4; ++i) {
            float4 v = *reinterpret_cast<const float4*>(A + (size_t)(mbase + ar + i * 32) * 512 + acc_);
            int p = ap + i * 32 * 36;
            As[p] = f2tff(v.x); As[p + 8] = f2tff(v.y); As[p + 16] = f2tff(v.z); As[p + 24] = f2tff(v.w);
        }
#pragma unroll
        for (int i = 0; i < 2; ++i) {
            float4 v = *reinterpret_cast<const float4*>(W + (size_t)(nbase + br + i * 32) * 512 + acc_);
            int p = bp + i * 32 * 36;
            Bs[p] = f2tff(v.x); Bs[p + 8] = f2tff(v.y); Bs[p + 16] = f2tff(v.z); Bs[p + 24] = f2tff(v.w);
        }
    }
    __syncthreads();

    for (int kt = 0; kt < 16; ++kt) {
        float* As = dyn + (kt & 1) * 6912;
        float* Bs = As + 4608;
        float* AsN = dyn + ((kt + 1) & 1) * 6912;
        float* BsN = AsN + 4608;

        float4 pa[4], pb[2];
        if (kt < 15) {
            int k0 = (kt + 1) * 32;
#pragma unroll
            for (int i = 0; i < 4; ++i)
                pa[i] = *reinterpret_cast<const float4*>(A + (size_t)(mbase + ar + i * 32) * 512 + k0 + acc_);
#pragma unroll
            for (int i = 0; i < 2; ++i)
                pb[i] = *reinterpret_cast<const float4*>(W + (size_t)(nbase + br + i * 32) * 512 + k0 + acc_);
        }

        unsigned a[2][4][4];
#pragma unroll
        for (int mt = 0; mt < 2; ++mt) {
            const float4* p0 = reinterpret_cast<const float4*>(As + (wm * 32 + mt * 16 + g    ) * 36 + tg * 8);
            const float4* p1 = reinterpret_cast<const float4*>(As + (wm * 32 + mt * 16 + g + 8) * 36 + tg * 8);
            float4 f0 = p0[0], f1 = p0[1];
            float4 f2 = p1[0], f3 = p1[1];
            a[mt][0][0] = u(f0.x); a[mt][0][1] = u(f2.x); a[mt][0][2] = u(f0.y); a[mt][0][3] = u(f2.y);
            a[mt][1][0] = u(f0.z); a[mt][1][1] = u(f2.z); a[mt][1][2] = u(f0.w); a[mt][1][3] = u(f2.w);
            a[mt][2][0] = u(f1.x); a[mt][2][1] = u(f3.x); a[mt][2][2] = u(f1.y); a[mt][2][3] = u(f3.y);
            a[mt][3][0] = u(f1.z); a[mt][3][1] = u(f3.z); a[mt][3][2] = u(f1.w); a[mt][3][3] = u(f3.w);
        }

#pragma unroll
        for (int kcp = 0; kcp < 2; ++kcp) {
            int kc0 = kcp * 2, kc1 = kcp * 2 + 1;
#pragma unroll
            for (int nt = 0; nt < 4; ++nt) {
                float4 f = reinterpret_cast<const float4*>(Bs + (wn * 32 + nt * 8 + g) * 36 + tg * 8)[kcp];
                mma_tf32(acc[0][nt][0], acc[0][nt][1], acc[0][nt][2], acc[0][nt][3],
                         a[0][kc0][0], a[0][kc0][1], a[0][kc0][2], a[0][kc0][3], u(f.x), u(f.y));
                mma_tf32(acc[1][nt][0], acc[1][nt][1], acc[1][nt][2], acc[1][nt][3],
                         a[1][kc0][0], a[1][kc0][1], a[1][kc0][2], a[1][kc0][3], u(f.x), u(f.y));
                mma_tf32(acc[0][nt][0], acc[0][nt][1], acc[0][nt][2], acc[0][nt][3],
                         a[0][kc1][0], a[0][kc1][1], a[0][kc1][2], a[0][kc1][3], u(f.z), u(f.w));
                mma_tf32(acc[1][nt][0], acc[1][nt][1], acc[1][nt][2], acc[1][nt][3],
                         a[1][kc1][0], a[1][kc1][1], a[1][kc1][2], a[1][kc1][3], u(f.z), u(f.w));
            }
        }

        if (kt < 15) {
#pragma unroll
            for (int i = 0; i < 4; ++i) {
                int p = ap + i * 32 * 36;
                AsN[p] = f2tff(pa[i].x); AsN[p + 8] = f2tff(pa[i].y);
                AsN[p + 16] = f2tff(pa[i].z); AsN[p + 24] = f2tff(pa[i].w);
            }
#pragma unroll
            for (int i = 0; i < 2; ++i) {
                int p = bp + i * 32 * 36;
                BsN[p] = f2tff(pb[i].x); BsN[p + 8] = f2tff(pb[i].y);
                BsN[p + 16] = f2tff(pb[i].z); BsN[p + 24] = f2tff(pb[i].w);
            }
        }
        __syncthreads();
    }

#pragma unroll
    for (int mt = 0; mt < 2; ++mt)
#pragma unroll
        for (int nt = 0; nt < 4; ++nt) {
            int col = nbase + wn * 32 + nt * 8 + 2 * tg;
            float b0 = bias[col], b1 = bias[col + 1];
            int r0 = mbase + wm * 32 + mt * 16 + g;
            int r1 = r0 + 8;
            float v00 = acc[mt][nt][0] + b0, v01 = acc[mt][nt][1] + b1;
            float v10 = acc[mt][nt][2] + b0, v11 = acc[mt][nt][3] + b1;
            if (cmode == 4) {
                __half* Ch = (blockIdx.x >= 8) ? g_V : g_K;
                int h = col >> 6, d = col & 63;
                {
                    int b = r0 >> 11, n = r0 & 2047;
                    __half* p = Ch + (size_t)(((b << 3) + h) * 2048 + n) * 64 + d;
                    *reinterpret_cast<__half2*>(p) = __floats2half2_rn(v00, v01);
                }
                {
                    int b = r1 >> 11, n = r1 & 2047;
                    __half* p = Ch + (size_t)(((b << 3) + h) * 2048 + n) * 64 + d;
                    *reinterpret_cast<__half2*>(p) = __floats2half2_rn(v10, v11);
                }
            } else if (cmode == 0) {
                int h = col >> 6, d = col & 63;
                {
                    int b = r0 >> 11, n = r0 & 2047;
                    float* p = g_Q + (size_t)(((b << 3) + h) * 2048 + n) * 64 + d;
                    *reinterpret_cast<float2*>(p) = make_float2(v00, v01);
                }
                {
                    int b = r1 >> 11, n = r1 & 2047;
                    float* p = g_Q + (size_t)(((b << 3) + h) * 2048 + n) * 64 + d;
                    *reinterpret_cast<float2*>(p) = make_float2(v10, v11);
                }
            } else {
                *reinterpret_cast<float2*>(Cext + (size_t)r0 * 512 + col) = make_float2(v00, v01);
                *reinterpret_cast<float2*>(Cext + (size_t)r1 * 512 + col) = make_float2(v10, v11);
            }
        }
}

// ============================================================
// Kernel 2: fp16 flash attention, cp.async staging, ldmatrix frags.
//  BM=64, BN=64, 128 threads, 2-stage, 3 CTAs/SM target.
//  K,V smem: row-major fp16 [64][64], 16B chunk c of row r at c^(r&7).
//  K frags: ldmatrix.x4 (non-trans); V frags: ldmatrix.x4.trans.
// ============================================================
__global__ __launch_bounds__(128, 3) void flash_kernel() {
    extern __shared__ float smf[];
    unsigned smb;
    asm("{ .reg .u64 t; cvta.to.shared.u64 t, %1; cvt.u32.u64 %0, t; }"
        : "=r"(smb) : "l"(smf));

    int tid = threadIdx.x, w = tid >> 5, lane = tid & 31;
    int g = lane >> 2, tg = lane & 3;
    int h = blockIdx.x, qt = blockIdx.y, bz = blockIdx.z;
    int bh = bz * 8 + h;
    const float*  Qb = g_Q + (size_t)bh * Nn * DH;
    const __half* Kb = g_K + (size_t)bh * Nn * DH;
    const __half* Vb = g_V + (size_t)bh * Nn * DH;
    int q0 = qt * 64;

    // cp.async staging map: thread -> rows (tid>>3)+16i, chunk tid&7
    int srow = tid >> 3, sch = tid & 7;
    int sgoff = srow * 128 + sch * 16;
    int sdoff = srow * 128 + ((sch ^ (srow & 7)) << 4);

    // K ldsm (non-trans) lane constants
    int i8 = lane & 7;
    int rowoff = ((lane >> 4) << 3) + i8;   // groups 2,3 -> +8 rows
    int choff = (lane >> 3) & 1;            // groups 1,3 -> +1 chunk
    // V ldsm (trans) lane constants
    int matq = lane >> 3;
    int vrowb = (((matq & 1) << 3) + i8) * 128;
    int chh = matq >> 1;

    // ---- stage Q tile [64,64] fp32, read fp16 A-fragments ----
#pragma unroll
    for (int i = 0; i < 8; ++i) {
        int idx = tid + i * 128;
        int r = idx >> 4, c = (idx & 15) * 4;
        float4 v = *reinterpret_cast<const float4*>(Qb + (size_t)(q0 + r) * 64 + c);
        *reinterpret_cast<float4*>(smf + r * 68 + c) = v;
    }
    __syncthreads();
    unsigned qa[4][4];
    {
        int r0 = w * 16 + g, r1 = r0 + 8;
#pragma unroll
        for (int kc = 0; kc < 4; ++kc) {
            float2 v0 = *reinterpret_cast<const float2*>(smf + r0 * 68 + kc * 16 + 2 * tg);
            float2 v1 = *reinterpret_cast<const float2*>(smf + r1 * 68 + kc * 16 + 2 * tg);
            float2 v2 = *reinterpret_cast<const float2*>(smf + r0 * 68 + kc * 16 + 2 * tg + 8);
            float2 v3 = *reinterpret_cast<const float2*>(smf + r1 * 68 + kc * 16 + 2 * tg + 8);
            qa[kc][0] = pack2(v0.x, v0.y);
            qa[kc][1] = pack2(v1.x, v1.y);
            qa[kc][2] = pack2(v2.x, v2.y);
            qa[kc][3] = pack2(v3.x, v3.y);
        }
    }
    __syncthreads();

    // ---- stage K/V kt=0 via cp.async ----
    {
        const char* Ksrc = (const char*)Kb;
        const char* Vsrc = (const char*)Vb;
#pragma unroll
        for (int i = 0; i < 4; ++i) {
            CP16(smb + sdoff + i * 2048,        Ksrc + sgoff + i * 2048);
            CP16(smb + 8192 + sdoff + i * 2048, Vsrc + sgoff + i * 2048);
        }
        asm volatile("cp.async.commit_group;");
        asm volatile("cp.async.wait_group 0;" ::: "memory");
    }
    __syncthreads();

    float accO[8][4];
#pragma unroll
    for (int ot = 0; ot < 8; ++ot)
#pragma unroll
        for (int i = 0; i < 4; ++i) accO[ot][i] = 0.f;
    float m0 = -1e30f, m1 = -1e30f, l0 = 0.f, l1 = 0.f;

    const float* G0 = g_G + ((size_t)bz * Nn + (q0 + w * 16 + g)) * Nn;
    const float* G1 = G0 + (size_t)8 * Nn;
    const float SL2 = SCALE_F * LOG2E;

    for (int kt = 0; kt < 32; ++kt) {
        unsigned kb = smb + (kt & 1) * 16384;
        unsigned vb = kb + 8192;

        // issue cp.async for kt+1 into the other stage
        if (kt < 31) {
            unsigned kbN = smb + ((kt + 1) & 1) * 16384;
            const char* Kn = (const char*)(Kb + (size_t)(kt + 1) * 4096);
            const char* Vn = (const char*)(Vb + (size_t)(kt + 1) * 4096);
#pragma unroll
            for (int i = 0; i < 4; ++i) {
                CP16(kbN + sdoff + i * 2048,        Kn + sgoff + i * 2048);
                CP16(kbN + 8192 + sdoff + i * 2048, Vn + sgoff + i * 2048);
            }
            asm volatile("cp.async.commit_group;");
        }

        // gate prefetch (consumed after QK)
        float2 gA[8], gB[8];
        {
            int cbase = kt * 64 + 2 * tg;
#pragma unroll
            for (int nt = 0; nt < 8; ++nt) {
                gA[nt] = *reinterpret_cast<const float2*>(G0 + cbase + nt * 8);
                gB[nt] = *reinterpret_cast<const float2*>(G1 + cbase + nt * 8);
            }
        }

        // ---- S = Q K^T : 4 k16-steps x 4 nt-pairs (ldsm4 non-trans) ----
        float sacc[8][4];
#pragma unroll
        for (int nt = 0; nt < 8; ++nt)
#pragma unroll
            for (int i = 0; i < 4; ++i) sacc[nt][i] = 0.f;
#pragma unroll
        for (int s = 0; s < 4; ++s) {
#pragma unroll
            for (int ntp = 0; ntp < 4; ++ntp) {
                unsigned b0, b1, b2, b3;
                unsigned addr = kb + (unsigned)((16 * ntp + rowoff) * 128
                                + (((2 * s + choff) ^ i8) << 4));
                ldsm4(b0, b1, b2, b3, addr);
                mma_f16(sacc[2 * ntp][0], sacc[2 * ntp][1], sacc[2 * ntp][2], sacc[2 * ntp][3],
                        qa[s][0], qa[s][1], qa[s][2], qa[s][3], b0, b1);
                mma_f16(sacc[2 * ntp + 1][0], sacc[2 * ntp + 1][1], sacc[2 * ntp + 1][2], sacc[2 * ntp + 1][3],
                        qa[s][0], qa[s][1], qa[s][2], qa[s][3], b2, b3);
            }
        }

        // logits: t = S*scale*log2e + log2(gate)
#pragma unroll
        for (int nt = 0; nt < 8; ++nt) {
            sacc[nt][0] = sacc[nt][0] * SL2 + gA[nt].x;
            sacc[nt][1] = sacc[nt][1] * SL2 + gA[nt].y;
            sacc[nt][2] = sacc[nt][2] * SL2 + gB[nt].x;
            sacc[nt][3] = sacc[nt][3] * SL2 + gB[nt].y;
        }

        // online softmax
        float mn0 = m0, mn1 = m1;
#pragma unroll
        for (int nt = 0; nt < 8; ++nt) {
            mn0 = fmaxf(mn0, fmaxf(sacc[nt][0], sacc[nt][1]));
            mn1 = fmaxf(mn1, fmaxf(sacc[nt][2], sacc[nt][3]));
        }
        mn0 = fmaxf(mn0, __shfl_xor_sync(0xffffffffu, mn0, 1));
        mn0 = fmaxf(mn0, __shfl_xor_sync(0xffffffffu, mn0, 2));
        mn1 = fmaxf(mn1, __shfl_xor_sync(0xffffffffu, mn1, 1));
        mn1 = fmaxf(mn1, __shfl_xor_sync(0xffffffffu, mn1, 2));
        float al0 = exp2f(m0 - mn0), al1 = exp2f(m1 - mn1);
        m0 = mn0; m1 = mn1;
        l0 *= al0; l1 *= al1;
#pragma unroll
        for (int ot = 0; ot < 8; ++ot) {
            accO[ot][0] *= al0; accO[ot][1] *= al0;
            accO[ot][2] *= al1; accO[ot][3] *= al1;
        }

        // P = exp2(t - m); accumulate l
#pragma unroll
        for (int nt = 0; nt < 8; ++nt) {
            sacc[nt][0] = exp2f(sacc[nt][0] - m0);
            sacc[nt][1] = exp2f(sacc[nt][1] - m0);
            sacc[nt][2] = exp2f(sacc[nt][2] - m1);
            sacc[nt][3] = exp2f(sacc[nt][3] - m1);
            l0 += sacc[nt][0] + sacc[nt][1];
            l1 += sacc[nt][2] + sacc[nt][3];
        }

        // ---- O += P@V : 4 k16-steps x 8 ot (B frags via ldsm4 trans) ----
#pragma unroll
        for (int s = 0; s < 4; ++s) {
            unsigned aP0 = pack2(sacc[2 * s][0],     sacc[2 * s][1]);
            unsigned aP1 = pack2(sacc[2 * s][2],     sacc[2 * s][3]);
            unsigned aP2 = pack2(sacc[2 * s + 1][0], sacc[2 * s + 1][1]);
            unsigned aP3 = pack2(sacc[2 * s + 1][2], sacc[2 * s + 1][3]);
            unsigned base_s = vb + s * 2048 + vrowb;
#pragma unroll
            for (int otp = 0; otp < 4; ++otp) {
                unsigned b0, b1, b2, b3;
                ldsm4t(b0, b1, b2, b3, base_s + ((((2 * otp + chh) ^ i8)) << 4));
                mma_f16(accO[2 * otp][0], accO[2 * otp][1], accO[2 * otp][2], accO[2 * otp][3],
                        aP0, aP1, aP2, aP3, b0, b1);
                mma_f16(accO[2 * otp + 1][0], accO[2 * otp + 1][1], accO[2 * otp + 1][2], accO[2 * otp + 1][3],
                        aP0, aP1, aP2, aP3, b2, b3);
            }
        }

        if (kt < 31)
            asm volatile("cp.async.wait_group 0;" ::: "memory");
        __syncthreads();
    }

    // quad-reduce the softmax denominators
    l0 += __shfl_xor_sync(0xffffffffu, l0, 1);
    l0 += __shfl_xor_sync(0xffffffffu, l0, 2);
    l1 += __shfl_xor_sync(0xffffffffu, l1, 1);
    l1 += __shfl_xor_sync(0xffffffffu, l1, 2);

    float inv0 = 1.0f / l0, inv1 = 1.0f / l1;
    int qr0 = q0 + w * 16 + g, qr1 = qr0 + 8;
    float* O0 = g_AO + ((size_t)(bz * Nn + qr0)) * DM + h * 64;
    float* O1 = g_AO + ((size_t)(bz * Nn + qr1)) * DM + h * 64;
#pragma unroll
    for (int ot = 0; ot < 8; ++ot) {
        int d = ot * 8 + 2 * tg;
        *reinterpret_cast<float2*>(O0 + d) = make_float2(accO[ot][0] * inv0, accO[ot][1] * inv0);
        *reinterpret_cast<float2*>(O1 + d) = make_float2(accO[ot][2] * inv1, accO[ot][3] * inv1);
    }
}

// ============================================================
extern "C" void kernel_launch(void* const* d_in, const int* in_sizes, int n_in,
                              void* d_out, int out_size) {
    const float* Qin  = (const float*)d_in[0];
    const float* KVin = (const float*)d_in[1];
    const float* SC   = (const float*)d_in[2];
    const float* Wq   = (const float*)d_in[3];
    const float* Wqb  = (const float*)d_in[4];
    const float* Wk   = (const float*)d_in[5];
    const float* Wkb  = (const float*)d_in[6];
    const float* Wv   = (const float*)d_in[7];
    const float* Wvb  = (const float*)d_in[8];
    const float* gw   = (const float*)d_in[9];
    const float* gb   = (const float*)d_in[10];
    const float* Wo   = (const float*)d_in[11];
    const float* Wob  = (const float*)d_in[12];
    float* out = (float*)d_out;

    cudaFuncSetAttribute(gemm512,      cudaFuncAttributeMaxDynamicSharedMemorySize, GEMM_SMEM);
    cudaFuncSetAttribute(flash_kernel, cudaFuncAttributeMaxDynamicSharedMemorySize, FLASH_SMEM);

    gate_kernel<<<16384, 256>>>(reinterpret_cast<const float4*>(SC), gw, gb);

    gemm512<<<dim3(8, 64),  256, GEMM_SMEM>>>(Qin,  Wq, Wqb, nullptr, nullptr, nullptr, 0, 0);
    gemm512<<<dim3(16, 64), 256, GEMM_SMEM>>>(KVin, Wk, Wkb, Wv,      Wvb,     nullptr, 0, 4);

    flash_kernel<<<dim3(8, 32, 4), 128, FLASH_SMEM>>>();

    gemm512<<<dim3(8, 64),  256, GEMM_SMEM>>>(nullptr, Wo, Wob, nullptr, nullptr, out, 1, 3);
}

// round 13
// speedup vs baseline: 3.0819x; 1.3884x over previous
#include <cuda_runtime.h>
#include <cuda_fp16.h>
#include <cstdint>

#define Bb   4
#define Nn   2048
#define DM   512
#define Hh   8
#define DH   64
#define SCALE_F 0.125f
#define LOG2E 1.4426950408889634f

#define GEMMH_SMEM 49152   // 2 stages x (A 128x64 fp16 = 16KB + B 64x64 fp16 = 8KB)
#define FLASH_SMEM 40960   // 2 stages x (K 8KB + V 8KB) + Q 8KB

// ---- scratch (static __device__, allocation-free) ----
__device__ float  g_G [(size_t)Bb * Nn * Nn];          // log2-gate, f32
__device__ __half g_Qh[(size_t)Bb * Hh * Nn * DH];     // Q  [bh][n][d] fp16
__device__ __half g_K [(size_t)Bb * Hh * Nn * DH];     // K  fp16
__device__ __half g_V [(size_t)Bb * Hh * Nn * DH];     // V  fp16
__device__ __half g_AO[(size_t)Bb * Nn * DM];          // attn out fp16
__device__ __half g_Wh[(size_t)4 * DM * DM];           // Wq|Wk|Wv|Wo fp16
__device__ __half g_A0[(size_t)Bb * Nn * DM];          // Q_input fp16
__device__ __half g_A1[(size_t)Bb * Nn * DM];          // KV_input fp16

// ---- helpers ----
__device__ __forceinline__ unsigned u(float x) { return __float_as_uint(x); }
__device__ __forceinline__ unsigned pack2(float lo, float hi) {
    __half2 h = __floats2half2_rn(lo, hi);
    return *reinterpret_cast<unsigned*>(&h);
}

#define CP16(dst, src) \
    asm volatile("cp.async.cg.shared.global [%0], [%1], 16;" :: "r"(dst), "l"(src))

__device__ __forceinline__ void mma_f16(float& d0, float& d1, float& d2, float& d3,
                                        unsigned a0, unsigned a1, unsigned a2, unsigned a3,
                                        unsigned b0, unsigned b1) {
    asm volatile(
        "mma.sync.aligned.m16n8k16.row.col.f32.f16.f16.f32 "
        "{%0,%1,%2,%3}, {%4,%5,%6,%7}, {%8,%9}, {%0,%1,%2,%3};"
        : "+f"(d0), "+f"(d1), "+f"(d2), "+f"(d3)
        : "r"(a0), "r"(a1), "r"(a2), "r"(a3), "r"(b0), "r"(b1));
}

__device__ __forceinline__ void ldsm4(unsigned& r0, unsigned& r1, unsigned& r2, unsigned& r3,
                                      unsigned addr) {
    asm volatile("ldmatrix.sync.aligned.m8n8.x4.shared.b16 {%0,%1,%2,%3}, [%4];"
                 : "=r"(r0), "=r"(r1), "=r"(r2), "=r"(r3) : "r"(addr));
}
__device__ __forceinline__ void ldsm4t(unsigned& r0, unsigned& r1, unsigned& r2, unsigned& r3,
                                       unsigned addr) {
    asm volatile("ldmatrix.sync.aligned.m8n8.x4.trans.shared.b16 {%0,%1,%2,%3}, [%4];"
                 : "=r"(r0), "=r"(r1), "=r"(r2), "=r"(r3) : "r"(addr));
}

// ============================================================
// Kernel A: f32 -> fp16 convert.  dsel: 0 -> g_Wh(+off4), 1 -> g_A0, 2 -> g_A1
// ============================================================
__global__ void cvt_kernel(const float4* __restrict__ src, int dsel, int off4) {
    int i = blockIdx.x * 256 + threadIdx.x;
    __half* base = (dsel == 0) ? g_Wh : (dsel == 1 ? g_A0 : g_A1);
    uint2* dst = reinterpret_cast<uint2*>(base) + off4;
    float4 v = src[i];
    uint2 o;
    o.x = pack2(v.x, v.y);
    o.y = pack2(v.z, v.w);
    dst[i] = o;
}

// ============================================================
// Kernel 0: gate precompute  G = log2(sigmoid(w*SC + b) + 1e-8)
// ============================================================
__global__ void gate_kernel(const float4* __restrict__ SC,
                            const float* __restrict__ gw,
                            const float* __restrict__ gb) {
    int i = blockIdx.x * 256 + threadIdx.x;
    float w = __ldg(gw), b = __ldg(gb);
    float4 s = SC[i];
    float4 r;
    r.x = __log2f(__fdividef(1.f, 1.f + __expf(-(s.x * w + b))) + 1e-8f);
    r.y = __log2f(__fdividef(1.f, 1.f + __expf(-(s.y * w + b))) + 1e-8f);
    r.z = __log2f(__fdividef(1.f, 1.f + __expf(-(s.z * w + b))) + 1e-8f);
    r.w = __log2f(__fdividef(1.f, 1.f + __expf(-(s.w * w + b))) + 1e-8f);
    reinterpret_cast<float4*>(g_G)[i] = r;
}

// ============================================================
// Kernel 1: fp16 GEMM  C[8192,512] = A @ W^T + bias
//  cp.async 2-stage, ldmatrix frags, m16n8k16.  k-tile 64 (8 iters).
//  smem rows: 64 halves = 8 x 16B chunks, chunk c of row r at c^(r&7).
//  amode: 0 -> g_A0, 1 -> g_A1, 2 -> g_AO
//  cmode: 0 -> g_Qh scatter ; 3 -> Cext f32 ; 4 -> fused K|V scatter
// ============================================================
__global__ __launch_bounds__(256, 2) void gemm_h(const float* __restrict__ biasa,
                                                 const float* __restrict__ biasb,
                                                 float* __restrict__ Cext,
                                                 int amode, int cmode) {
    extern __shared__ char smc[];
    unsigned smb;
    asm("{ .reg .u64 t; cvta.to.shared.u64 t, %1; cvt.u32.u64 %0, t; }"
        : "=r"(smb) : "l"(smc));

    const __half* A = (amode == 0) ? g_A0 : (amode == 1 ? g_A1 : g_AO);
    const __half* W;
    const float* bias;
    if (cmode == 0)      { W = g_Wh;                bias = biasa; }
    else if (cmode == 3) { W = g_Wh + 3 * DM * DM;  bias = biasa; }
    else {  // cmode 4: fused K|V
        if (blockIdx.x >= 8) { W = g_Wh + 2 * DM * DM; bias = biasb; }
        else                 { W = g_Wh + 1 * DM * DM; bias = biasa; }
    }

    int tid  = threadIdx.x;
    int warp = tid >> 5, lane = tid & 31;
    int g = lane >> 2, tg = lane & 3;
    int wm = warp >> 1, wn = warp & 1;
    int mbase = blockIdx.y * 128, nbase = (blockIdx.x & 7) * 64;

    // staging map: 8 threads per row, 16B chunk each
    int srow = tid >> 3, sch = tid & 7;          // srow 0..31
    int sdoff = ((sch ^ (srow & 7)) << 4);

    // ldsm lane constants
    int i8 = lane & 7;
    int la = lane & 15, ca = lane >> 4;                 // A frag map
    int rowoffB = ((lane >> 4) << 3) + i8;              // B frag map
    int choffB  = (lane >> 3) & 1;

    float acc[2][4][4];
#pragma unroll
    for (int mt = 0; mt < 2; ++mt)
#pragma unroll
        for (int nt = 0; nt < 4; ++nt)
#pragma unroll
            for (int i = 0; i < 4; ++i) acc[mt][nt][i] = 0.f;

    // ---- prologue: stage kt=0 ----
    {
#pragma unroll
        for (int i = 0; i < 4; ++i) {
            int r = srow + 32 * i;
            CP16(smb + r * 128 + sdoff,
                 (const char*)(A + (size_t)(mbase + r) * 512) + sch * 16);
        }
#pragma unroll
        for (int i = 0; i < 2; ++i) {
            int r = srow + 32 * i;
            CP16(smb + 16384 + r * 128 + sdoff,
                 (const char*)(W + (size_t)(nbase + r) * 512) + sch * 16);
        }
        asm volatile("cp.async.commit_group;");
        asm volatile("cp.async.wait_group 0;" ::: "memory");
    }
    __syncthreads();

    for (int kt = 0; kt < 8; ++kt) {
        unsigned Ab = smb + (kt & 1) * 24576;
        unsigned Bsm = Ab + 16384;

        if (kt < 7) {
            unsigned AbN = smb + ((kt + 1) & 1) * 24576;
            int kh = (kt + 1) * 64;
#pragma unroll
            for (int i = 0; i < 4; ++i) {
                int r = srow + 32 * i;
                CP16(AbN + r * 128 + sdoff,
                     (const char*)(A + (size_t)(mbase + r) * 512 + kh) + sch * 16);
            }
#pragma unroll
            for (int i = 0; i < 2; ++i) {
                int r = srow + 32 * i;
                CP16(AbN + 16384 + r * 128 + sdoff,
                     (const char*)(W + (size_t)(nbase + r) * 512 + kh) + sch * 16);
            }
            asm volatile("cp.async.commit_group;");
        }

        // A fragments: [mt][s]
        unsigned af[2][4][4];
#pragma unroll
        for (int mt = 0; mt < 2; ++mt) {
            int row = wm * 32 + mt * 16 + la;
#pragma unroll
            for (int s = 0; s < 4; ++s)
                ldsm4(af[mt][s][0], af[mt][s][1], af[mt][s][2], af[mt][s][3],
                      Ab + row * 128 + ((((2 * s + ca)) ^ (row & 7)) << 4));
        }

        // B fragments + MMA, per n16 group
#pragma unroll
        for (int ntp = 0; ntp < 2; ++ntp) {
            int rowb = wn * 32 + ntp * 16 + rowoffB;
            unsigned bf[4][4];
#pragma unroll
            for (int s = 0; s < 4; ++s)
                ldsm4(bf[s][0], bf[s][1], bf[s][2], bf[s][3],
                      Bsm + rowb * 128 + ((((2 * s + choffB)) ^ (rowb & 7)) << 4));
#pragma unroll
            for (int s = 0; s < 4; ++s) {
#pragma unroll
                for (int mt = 0; mt < 2; ++mt) {
                    mma_f16(acc[mt][2 * ntp][0], acc[mt][2 * ntp][1],
                            acc[mt][2 * ntp][2], acc[mt][2 * ntp][3],
                            af[mt][s][0], af[mt][s][1], af[mt][s][2], af[mt][s][3],
                            bf[s][0], bf[s][1]);
                    mma_f16(acc[mt][2 * ntp + 1][0], acc[mt][2 * ntp + 1][1],
                            acc[mt][2 * ntp + 1][2], acc[mt][2 * ntp + 1][3],
                            af[mt][s][0], af[mt][s][1], af[mt][s][2], af[mt][s][3],
                            bf[s][2], bf[s][3]);
                }
            }
        }

        if (kt < 7)
            asm volatile("cp.async.wait_group 0;" ::: "memory");
        __syncthreads();
    }

    // ---- epilogue ----
#pragma unroll
    for (int mt = 0; mt < 2; ++mt)
#pragma unroll
        for (int nt = 0; nt < 4; ++nt) {
            int col = nbase + wn * 32 + nt * 8 + 2 * tg;
            float b0 = bias[col], b1 = bias[col + 1];
            int r0 = mbase + wm * 32 + mt * 16 + g;
            int r1 = r0 + 8;
            float v00 = acc[mt][nt][0] + b0, v01 = acc[mt][nt][1] + b1;
            float v10 = acc[mt][nt][2] + b0, v11 = acc[mt][nt][3] + b1;
            if (cmode == 3) {
                *reinterpret_cast<float2*>(Cext + (size_t)r0 * 512 + col) = make_float2(v00, v01);
                *reinterpret_cast<float2*>(Cext + (size_t)r1 * 512 + col) = make_float2(v10, v11);
            } else {
                __half* Ch = (cmode == 0) ? g_Qh : ((blockIdx.x >= 8) ? g_V : g_K);
                int h = col >> 6, d = col & 63;
                {
                    int b = r0 >> 11, n = r0 & 2047;
                    __half* p = Ch + (size_t)(((b << 3) + h) * 2048 + n) * 64 + d;
                    *reinterpret_cast<__half2*>(p) = __floats2half2_rn(v00, v01);
                }
                {
                    int b = r1 >> 11, n = r1 & 2047;
                    __half* p = Ch + (size_t)(((b << 3) + h) * 2048 + n) * 64 + d;
                    *reinterpret_cast<__half2*>(p) = __floats2half2_rn(v10, v11);
                }
            }
        }
}

// ============================================================
// Kernel 2: fp16 flash attention (R12 core; Q now fp16 via cp.async+ldsm)
// ============================================================
__global__ __launch_bounds__(128, 3) void flash_kernel() {
    extern __shared__ char smc[];
    unsigned smb;
    asm("{ .reg .u64 t; cvta.to.shared.u64 t, %1; cvt.u32.u64 %0, t; }"
        : "=r"(smb) : "l"(smc));

    int tid = threadIdx.x, w = tid >> 5, lane = tid & 31;
    int g = lane >> 2, tg = lane & 3;
    int h = blockIdx.x, qt = blockIdx.y, bz = blockIdx.z;
    int bh = bz * 8 + h;
    const __half* Qb = g_Qh + (size_t)bh * Nn * DH;
    const __half* Kb = g_K  + (size_t)bh * Nn * DH;
    const __half* Vb = g_V  + (size_t)bh * Nn * DH;
    int q0 = qt * 64;

    // staging map (Q/K/V identical): 8 threads per row, rows srow+16i
    int srow = tid >> 3, sch = tid & 7;
    int sgoff = srow * 128 + sch * 16;
    int sdoff = srow * 128 + ((sch ^ (srow & 7)) << 4);

    // ldsm lane constants
    int i8 = lane & 7;
    int la = lane & 15, ca = lane >> 4;           // A-frag (Q)
    int rowoff = ((lane >> 4) << 3) + i8;          // B-frag (K)
    int choff = (lane >> 3) & 1;
    int matq = lane >> 3;                          // V trans
    int vrowb = (((matq & 1) << 3) + i8) * 128;
    int chh = matq >> 1;

    // ---- prologue: Q + K/V stage0 via cp.async ----
    {
        const char* Qsrc = (const char*)(Qb + (size_t)q0 * 64);
        const char* Ksrc = (const char*)Kb;
        const char* Vsrc = (const char*)Vb;
#pragma unroll
        for (int i = 0; i < 4; ++i) {
            CP16(smb + 32768 + sdoff + i * 2048, Qsrc + sgoff + i * 2048);
            CP16(smb + sdoff + i * 2048,         Ksrc + sgoff + i * 2048);
            CP16(smb + 8192 + sdoff + i * 2048,  Vsrc + sgoff + i * 2048);
        }
        asm volatile("cp.async.commit_group;");
        asm volatile("cp.async.wait_group 0;" ::: "memory");
    }
    __syncthreads();

    // Q fragments (A layout): rows w*16..w*16+15
    unsigned qa[4][4];
    {
        int qrow = w * 16 + la;
#pragma unroll
        for (int s = 0; s < 4; ++s)
            ldsm4(qa[s][0], qa[s][1], qa[s][2], qa[s][3],
                  smb + 32768 + qrow * 128 + ((((2 * s + ca)) ^ (qrow & 7)) << 4));
    }

    float accO[8][4];
#pragma unroll
    for (int ot = 0; ot < 8; ++ot)
#pragma unroll
        for (int i = 0; i < 4; ++i) accO[ot][i] = 0.f;
    float m0 = -1e30f, m1 = -1e30f, l0 = 0.f, l1 = 0.f;

    const float* G0 = g_G + ((size_t)bz * Nn + (q0 + w * 16 + g)) * Nn;
    const float* G1 = G0 + (size_t)8 * Nn;
    const float SL2 = SCALE_F * LOG2E;

    for (int kt = 0; kt < 32; ++kt) {
        unsigned kb = smb + (kt & 1) * 16384;
        unsigned vb = kb + 8192;

        if (kt < 31) {
            unsigned kbN = smb + ((kt + 1) & 1) * 16384;
            const char* Kn = (const char*)(Kb + (size_t)(kt + 1) * 4096);
            const char* Vn = (const char*)(Vb + (size_t)(kt + 1) * 4096);
#pragma unroll
            for (int i = 0; i < 4; ++i) {
                CP16(kbN + sdoff + i * 2048,        Kn + sgoff + i * 2048);
                CP16(kbN + 8192 + sdoff + i * 2048, Vn + sgoff + i * 2048);
            }
            asm volatile("cp.async.commit_group;");
        }

        // gate prefetch (consumed after QK)
        float2 gA[8], gB[8];
        {
            int cbase = kt * 64 + 2 * tg;
#pragma unroll
            for (int nt = 0; nt < 8; ++nt) {
                gA[nt] = *reinterpret_cast<const float2*>(G0 + cbase + nt * 8);
                gB[nt] = *reinterpret_cast<const float2*>(G1 + cbase + nt * 8);
            }
        }

        // ---- S = Q K^T ----
        float sacc[8][4];
#pragma unroll
        for (int nt = 0; nt < 8; ++nt)
#pragma unroll
            for (int i = 0; i < 4; ++i) sacc[nt][i] = 0.f;
#pragma unroll
        for (int s = 0; s < 4; ++s) {
#pragma unroll
            for (int ntp = 0; ntp < 4; ++ntp) {
                unsigned b0, b1, b2, b3;
                unsigned addr = kb + (unsigned)((16 * ntp + rowoff) * 128
                                + (((2 * s + choff) ^ i8) << 4));
                ldsm4(b0, b1, b2, b3, addr);
                mma_f16(sacc[2 * ntp][0], sacc[2 * ntp][1], sacc[2 * ntp][2], sacc[2 * ntp][3],
                        qa[s][0], qa[s][1], qa[s][2], qa[s][3], b0, b1);
                mma_f16(sacc[2 * ntp + 1][0], sacc[2 * ntp + 1][1], sacc[2 * ntp + 1][2], sacc[2 * ntp + 1][3],
                        qa[s][0], qa[s][1], qa[s][2], qa[s][3], b2, b3);
            }
        }

        // logits
#pragma unroll
        for (int nt = 0; nt < 8; ++nt) {
            sacc[nt][0] = sacc[nt][0] * SL2 + gA[nt].x;
            sacc[nt][1] = sacc[nt][1] * SL2 + gA[nt].y;
            sacc[nt][2] = sacc[nt][2] * SL2 + gB[nt].x;
            sacc[nt][3] = sacc[nt][3] * SL2 + gB[nt].y;
        }

        // online softmax
        float mn0 = m0, mn1 = m1;
#pragma unroll
        for (int nt = 0; nt < 8; ++nt) {
            mn0 = fmaxf(mn0, fmaxf(sacc[nt][0], sacc[nt][1]));
            mn1 = fmaxf(mn1, fmaxf(sacc[nt][2], sacc[nt][3]));
        }
        mn0 = fmaxf(mn0, __shfl_xor_sync(0xffffffffu, mn0, 1));
        mn0 = fmaxf(mn0, __shfl_xor_sync(0xffffffffu, mn0, 2));
        mn1 = fmaxf(mn1, __shfl_xor_sync(0xffffffffu, mn1, 1));
        mn1 = fmaxf(mn1, __shfl_xor_sync(0xffffffffu, mn1, 2));
        float al0 = exp2f(m0 - mn0), al1 = exp2f(m1 - mn1);
        m0 = mn0; m1 = mn1;
        l0 *= al0; l1 *= al1;
#pragma unroll
        for (int ot = 0; ot < 8; ++ot) {
            accO[ot][0] *= al0; accO[ot][1] *= al0;
            accO[ot][2] *= al1; accO[ot][3] *= al1;
        }

        // P = exp2(t - m); accumulate l
#pragma unroll
        for (int nt = 0; nt < 8; ++nt) {
            sacc[nt][0] = exp2f(sacc[nt][0] - m0);
            sacc[nt][1] = exp2f(sacc[nt][1] - m0);
            sacc[nt][2] = exp2f(sacc[nt][2] - m1);
            sacc[nt][3] = exp2f(sacc[nt][3] - m1);
            l0 += sacc[nt][0] + sacc[nt][1];
            l1 += sacc[nt][2] + sacc[nt][3];
        }

        // ---- O += P@V ----
#pragma unroll
        for (int s = 0; s < 4; ++s) {
            unsigned aP0 = pack2(sacc[2 * s][0],     sacc[2 * s][1]);
            unsigned aP1 = pack2(sacc[2 * s][2],     sacc[2 * s][3]);
            unsigned aP2 = pack2(sacc[2 * s + 1][0], sacc[2 * s + 1][1]);
            unsigned aP3 = pack2(sacc[2 * s + 1][2], sacc[2 * s + 1][3]);
            unsigned base_s = vb + s * 2048 + vrowb;
#pragma unroll
            for (int otp = 0; otp < 4; ++otp) {
                unsigned b0, b1, b2, b3;
                ldsm4t(b0, b1, b2, b3, base_s + ((((2 * otp + chh) ^ i8)) << 4));
                mma_f16(accO[2 * otp][0], accO[2 * otp][1], accO[2 * otp][2], accO[2 * otp][3],
                        aP0, aP1, aP2, aP3, b0, b1);
                mma_f16(accO[2 * otp + 1][0], accO[2 * otp + 1][1], accO[2 * otp + 1][2], accO[2 * otp + 1][3],
                        aP0, aP1, aP2, aP3, b2, b3);
            }
        }

        if (kt < 31)
            asm volatile("cp.async.wait_group 0;" ::: "memory");
        __syncthreads();
    }

    // quad-reduce denominators
    l0 += __shfl_xor_sync(0xffffffffu, l0, 1);
    l0 += __shfl_xor_sync(0xffffffffu, l0, 2);
    l1 += __shfl_xor_sync(0xffffffffu, l1, 1);
    l1 += __shfl_xor_sync(0xffffffffu, l1, 2);

    float inv0 = 1.0f / l0, inv1 = 1.0f / l1;
    int qr0 = q0 + w * 16 + g, qr1 = qr0 + 8;
    __half* O0 = g_AO + ((size_t)(bz * Nn + qr0)) * DM + h * 64;
    __half* O1 = g_AO + ((size_t)(bz * Nn + qr1)) * DM + h * 64;
#pragma unroll
    for (int ot = 0; ot < 8; ++ot) {
        int d = ot * 8 + 2 * tg;
        *reinterpret_cast<__half2*>(O0 + d) = __floats2half2_rn(accO[ot][0] * inv0, accO[ot][1] * inv0);
        *reinterpret_cast<__half2*>(O1 + d) = __floats2half2_rn(accO[ot][2] * inv1, accO[ot][3] * inv1);
    }
}

// ============================================================
extern "C" void kernel_launch(void* const* d_in, const int* in_sizes, int n_in,
                              void* d_out, int out_size) {
    const float* Qin  = (const float*)d_in[0];
    const float* KVin = (const float*)d_in[1];
    const float* SC   = (const float*)d_in[2];
    const float* Wq   = (const float*)d_in[3];
    const float* Wqb  = (const float*)d_in[4];
    const float* Wk   = (const float*)d_in[5];
    const float* Wkb  = (const float*)d_in[6];
    const float* Wv   = (const float*)d_in[7];
    const float* Wvb  = (const float*)d_in[8];
    const float* gw   = (const float*)d_in[9];
    const float* gb   = (const float*)d_in[10];
    const float* Wo   = (const float*)d_in[11];
    const float* Wob  = (const float*)d_in[12];
    float* out = (float*)d_out;

    cudaFuncSetAttribute(gemm_h,       cudaFuncAttributeMaxDynamicSharedMemorySize, GEMMH_SMEM);
    cudaFuncSetAttribute(flash_kernel, cudaFuncAttributeMaxDynamicSharedMemorySize, FLASH_SMEM);

    // one-time fp16 conversions (weights + inputs)
    cvt_kernel<<<256, 256>>>(reinterpret_cast<const float4*>(Wq), 0, 0 * 65536);
    cvt_kernel<<<256, 256>>>(reinterpret_cast<const float4*>(Wk), 0, 1 * 65536);
    cvt_kernel<<<256, 256>>>(reinterpret_cast<const float4*>(Wv), 0, 2 * 65536);
    cvt_kernel<<<256, 256>>>(reinterpret_cast<const float4*>(Wo), 0, 3 * 65536);
    cvt_kernel<<<4096, 256>>>(reinterpret_cast<const float4*>(Qin),  1, 0);
    cvt_kernel<<<4096, 256>>>(reinterpret_cast<const float4*>(KVin), 2, 0);

    gate_kernel<<<16384, 256>>>(reinterpret_cast<const float4*>(SC), gw, gb);

    gemm_h<<<dim3(8, 64),  256, GEMMH_SMEM>>>(Wqb, nullptr, nullptr, 0, 0);
    gemm_h<<<dim3(16, 64), 256, GEMMH_SMEM>>>(Wkb, Wvb,     nullptr, 1, 4);

    flash_kernel<<<dim3(8, 32, 4), 128, FLASH_SMEM>>>();

    gemm_h<<<dim3(8, 64),  256, GEMMH_SMEM>>>(Wob, nullptr, out, 2, 3);
}

// round 14
// speedup vs baseline: 3.2105x; 1.0417x over previous
#include <cuda_runtime.h>
#include <cuda_fp16.h>
#include <cstdint>

#define Bb   4
#define Nn   2048
#define DM   512
#define Hh   8
#define DH   64
#define SCALE_F 0.125f
#define LOG2E 1.4426950408889634f

#define GEMMH_SMEM 49152   // 2 stages x (A 128x64 fp16 = 16KB + B 64x64 fp16 = 8KB)
#define FLASH_SMEM 40960   // 2 stages x (K 8KB + V 8KB) + Q 8KB

// ---- scratch (static __device__, allocation-free) ----
__device__ __half g_G [(size_t)Bb * Nn * Nn];          // log2-gate, fp16 (33.5 MB)
__device__ __half g_Qh[(size_t)Bb * Hh * Nn * DH];     // Q  [bh][n][d] fp16
__device__ __half g_K [(size_t)Bb * Hh * Nn * DH];     // K  fp16
__device__ __half g_V [(size_t)Bb * Hh * Nn * DH];     // V  fp16
__device__ __half g_AO[(size_t)Bb * Nn * DM];          // attn out fp16
__device__ __half g_Wh[(size_t)4 * DM * DM];           // Wq|Wk|Wv|Wo fp16
__device__ __half g_A0[(size_t)Bb * Nn * DM];          // Q_input fp16
__device__ __half g_A1[(size_t)Bb * Nn * DM];          // KV_input fp16

// ---- helpers ----
__device__ __forceinline__ unsigned u(float x) { return __float_as_uint(x); }
__device__ __forceinline__ unsigned pack2(float lo, float hi) {
    __half2 h = __floats2half2_rn(lo, hi);
    return *reinterpret_cast<unsigned*>(&h);
}

#define CP16(dst, src) \
    asm volatile("cp.async.cg.shared.global [%0], [%1], 16;" :: "r"(dst), "l"(src))

__device__ __forceinline__ void mma_f16(float& d0, float& d1, float& d2, float& d3,
                                        unsigned a0, unsigned a1, unsigned a2, unsigned a3,
                                        unsigned b0, unsigned b1) {
    asm volatile(
        "mma.sync.aligned.m16n8k16.row.col.f32.f16.f16.f32 "
        "{%0,%1,%2,%3}, {%4,%5,%6,%7}, {%8,%9}, {%0,%1,%2,%3};"
        : "+f"(d0), "+f"(d1), "+f"(d2), "+f"(d3)
        : "r"(a0), "r"(a1), "r"(a2), "r"(a3), "r"(b0), "r"(b1));
}

__device__ __forceinline__ void ldsm4(unsigned& r0, unsigned& r1, unsigned& r2, unsigned& r3,
                                      unsigned addr) {
    asm volatile("ldmatrix.sync.aligned.m8n8.x4.shared.b16 {%0,%1,%2,%3}, [%4];"
                 : "=r"(r0), "=r"(r1), "=r"(r2), "=r"(r3) : "r"(addr));
}
__device__ __forceinline__ void ldsm4t(unsigned& r0, unsigned& r1, unsigned& r2, unsigned& r3,
                                       unsigned addr) {
    asm volatile("ldmatrix.sync.aligned.m8n8.x4.trans.shared.b16 {%0,%1,%2,%3}, [%4];"
                 : "=r"(r0), "=r"(r1), "=r"(r2), "=r"(r3) : "r"(addr));
}

// ============================================================
// Kernel A: fused f32 -> fp16 convert for ALL weights + inputs.
//  blocks [0,1024): Wq|Wk|Wv|Wo -> g_Wh   (256 blocks each)
//  blocks [1024,5120): Qin  -> g_A0
//  blocks [5120,9216): KVin -> g_A1
// ============================================================
__global__ void cvt_all(const float4* __restrict__ Wq, const float4* __restrict__ Wk,
                        const float4* __restrict__ Wv, const float4* __restrict__ Wo,
                        const float4* __restrict__ Qin, const float4* __restrict__ KVin) {
    int b = blockIdx.x;
    const float4* src;
    uint2* dst;
    int i;
    if (b < 1024) {
        int seg = b >> 8;
        i = (b & 255) * 256 + threadIdx.x;
        src = (seg == 0) ? Wq : (seg == 1) ? Wk : (seg == 2) ? Wv : Wo;
        dst = reinterpret_cast<uint2*>(g_Wh) + seg * 65536;
    } else if (b < 5120) {
        i = (b - 1024) * 256 + threadIdx.x;
        src = Qin;  dst = reinterpret_cast<uint2*>(g_A0);
    } else {
        i = (b - 5120) * 256 + threadIdx.x;
        src = KVin; dst = reinterpret_cast<uint2*>(g_A1);
    }
    float4 v = src[i];
    uint2 o;
    o.x = pack2(v.x, v.y);
    o.y = pack2(v.z, v.w);
    dst[i] = o;
}

// ============================================================
// Kernel 0: gate precompute  G = (half) log2(sigmoid(w*SC + b) + 1e-8)
// ============================================================
__global__ void gate_kernel(const float4* __restrict__ SC,
                            const float* __restrict__ gw,
                            const float* __restrict__ gb) {
    int i = blockIdx.x * 256 + threadIdx.x;
    float w = __ldg(gw), b = __ldg(gb);
    float4 s = SC[i];
    float rx = __log2f(__fdividef(1.f, 1.f + __expf(-(s.x * w + b))) + 1e-8f);
    float ry = __log2f(__fdividef(1.f, 1.f + __expf(-(s.y * w + b))) + 1e-8f);
    float rz = __log2f(__fdividef(1.f, 1.f + __expf(-(s.z * w + b))) + 1e-8f);
    float rw = __log2f(__fdividef(1.f, 1.f + __expf(-(s.w * w + b))) + 1e-8f);
    uint2 o;
    o.x = pack2(rx, ry);
    o.y = pack2(rz, rw);
    reinterpret_cast<uint2*>(g_G)[i] = o;
}

// ============================================================
// Kernel 1: fp16 GEMM  C[8192,512] = A @ W^T + bias  (R13, unchanged)
// ============================================================
__global__ __launch_bounds__(256, 2) void gemm_h(const float* __restrict__ biasa,
                                                 const float* __restrict__ biasb,
                                                 float* __restrict__ Cext,
                                                 int amode, int cmode) {
    extern __shared__ char smc[];
    unsigned smb;
    asm("{ .reg .u64 t; cvta.to.shared.u64 t, %1; cvt.u32.u64 %0, t; }"
        : "=r"(smb) : "l"(smc));

    const __half* A = (amode == 0) ? g_A0 : (amode == 1 ? g_A1 : g_AO);
    const __half* W;
    const float* bias;
    if (cmode == 0)      { W = g_Wh;                bias = biasa; }
    else if (cmode == 3) { W = g_Wh + 3 * DM * DM;  bias = biasa; }
    else {
        if (blockIdx.x >= 8) { W = g_Wh + 2 * DM * DM; bias = biasb; }
        else                 { W = g_Wh + 1 * DM * DM; bias = biasa; }
    }

    int tid  = threadIdx.x;
    int warp = tid >> 5, lane = tid & 31;
    int g = lane >> 2, tg = lane & 3;
    int wm = warp >> 1, wn = warp & 1;
    int mbase = blockIdx.y * 128, nbase = (blockIdx.x & 7) * 64;

    int srow = tid >> 3, sch = tid & 7;
    int sdoff = ((sch ^ (srow & 7)) << 4);

    int i8 = lane & 7;
    int la = lane & 15, ca = lane >> 4;
    int rowoffB = ((lane >> 4) << 3) + i8;
    int choffB  = (lane >> 3) & 1;

    float acc[2][4][4];
#pragma unroll
    for (int mt = 0; mt < 2; ++mt)
#pragma unroll
        for (int nt = 0; nt < 4; ++nt)
#pragma unroll
            for (int i = 0; i < 4; ++i) acc[mt][nt][i] = 0.f;

    {
#pragma unroll
        for (int i = 0; i < 4; ++i) {
            int r = srow + 32 * i;
            CP16(smb + r * 128 + sdoff,
                 (const char*)(A + (size_t)(mbase + r) * 512) + sch * 16);
        }
#pragma unroll
        for (int i = 0; i < 2; ++i) {
            int r = srow + 32 * i;
            CP16(smb + 16384 + r * 128 + sdoff,
                 (const char*)(W + (size_t)(nbase + r) * 512) + sch * 16);
        }
        asm volatile("cp.async.commit_group;");
        asm volatile("cp.async.wait_group 0;" ::: "memory");
    }
    __syncthreads();

    for (int kt = 0; kt < 8; ++kt) {
        unsigned Ab = smb + (kt & 1) * 24576;
        unsigned Bsm = Ab + 16384;

        if (kt < 7) {
            unsigned AbN = smb + ((kt + 1) & 1) * 24576;
            int kh = (kt + 1) * 64;
#pragma unroll
            for (int i = 0; i < 4; ++i) {
                int r = srow + 32 * i;
                CP16(AbN + r * 128 + sdoff,
                     (const char*)(A + (size_t)(mbase + r) * 512 + kh) + sch * 16);
            }
#pragma unroll
            for (int i = 0; i < 2; ++i) {
                int r = srow + 32 * i;
                CP16(AbN + 16384 + r * 128 + sdoff,
                     (const char*)(W + (size_t)(nbase + r) * 512 + kh) + sch * 16);
            }
            asm volatile("cp.async.commit_group;");
        }

        unsigned af[2][4][4];
#pragma unroll
        for (int mt = 0; mt < 2; ++mt) {
            int row = wm * 32 + mt * 16 + la;
#pragma unroll
            for (int s = 0; s < 4; ++s)
                ldsm4(af[mt][s][0], af[mt][s][1], af[mt][s][2], af[mt][s][3],
                      Ab + row * 128 + ((((2 * s + ca)) ^ (row & 7)) << 4));
        }

#pragma unroll
        for (int ntp = 0; ntp < 2; ++ntp) {
            int rowb = wn * 32 + ntp * 16 + rowoffB;
            unsigned bf[4][4];
#pragma unroll
            for (int s = 0; s < 4; ++s)
                ldsm4(bf[s][0], bf[s][1], bf[s][2], bf[s][3],
                      Bsm + rowb * 128 + ((((2 * s + choffB)) ^ (rowb & 7)) << 4));
#pragma unroll
            for (int s = 0; s < 4; ++s) {
#pragma unroll
                for (int mt = 0; mt < 2; ++mt) {
                    mma_f16(acc[mt][2 * ntp][0], acc[mt][2 * ntp][1],
                            acc[mt][2 * ntp][2], acc[mt][2 * ntp][3],
                            af[mt][s][0], af[mt][s][1], af[mt][s][2], af[mt][s][3],
                            bf[s][0], bf[s][1]);
                    mma_f16(acc[mt][2 * ntp + 1][0], acc[mt][2 * ntp + 1][1],
                            acc[mt][2 * ntp + 1][2], acc[mt][2 * ntp + 1][3],
                            af[mt][s][0], af[mt][s][1], af[mt][s][2], af[mt][s][3],
                            bf[s][2], bf[s][3]);
                }
            }
        }

        if (kt < 7)
            asm volatile("cp.async.wait_group 0;" ::: "memory");
        __syncthreads();
    }

#pragma unroll
    for (int mt = 0; mt < 2; ++mt)
#pragma unroll
        for (int nt = 0; nt < 4; ++nt) {
            int col = nbase + wn * 32 + nt * 8 + 2 * tg;
            float b0 = bias[col], b1 = bias[col + 1];
            int r0 = mbase + wm * 32 + mt * 16 + g;
            int r1 = r0 + 8;
            float v00 = acc[mt][nt][0] + b0, v01 = acc[mt][nt][1] + b1;
            float v10 = acc[mt][nt][2] + b0, v11 = acc[mt][nt][3] + b1;
            if (cmode == 3) {
                *reinterpret_cast<float2*>(Cext + (size_t)r0 * 512 + col) = make_float2(v00, v01);
                *reinterpret_cast<float2*>(Cext + (size_t)r1 * 512 + col) = make_float2(v10, v11);
            } else {
                __half* Ch = (cmode == 0) ? g_Qh : ((blockIdx.x >= 8) ? g_V : g_K);
                int h = col >> 6, d = col & 63;
                {
                    int b = r0 >> 11, n = r0 & 2047;
                    __half* p = Ch + (size_t)(((b << 3) + h) * 2048 + n) * 64 + d;
                    *reinterpret_cast<__half2*>(p) = __floats2half2_rn(v00, v01);
                }
                {
                    int b = r1 >> 11, n = r1 & 2047;
                    __half* p = Ch + (size_t)(((b << 3) + h) * 2048 + n) * 64 + d;
                    *reinterpret_cast<__half2*>(p) = __floats2half2_rn(v10, v11);
                }
            }
        }
}

// ============================================================
// Kernel 2: fp16 flash attention (R13 core; gate now fp16)
// ============================================================
__global__ __launch_bounds__(128, 3) void flash_kernel() {
    extern __shared__ char smc[];
    unsigned smb;
    asm("{ .reg .u64 t; cvta.to.shared.u64 t, %1; cvt.u32.u64 %0, t; }"
        : "=r"(smb) : "l"(smc));

    int tid = threadIdx.x, w = tid >> 5, lane = tid & 31;
    int g = lane >> 2, tg = lane & 3;
    int h = blockIdx.x, qt = blockIdx.y, bz = blockIdx.z;
    int bh = bz * 8 + h;
    const __half* Qb = g_Qh + (size_t)bh * Nn * DH;
    const __half* Kb = g_K  + (size_t)bh * Nn * DH;
    const __half* Vb = g_V  + (size_t)bh * Nn * DH;
    int q0 = qt * 64;

    int srow = tid >> 3, sch = tid & 7;
    int sgoff = srow * 128 + sch * 16;
    int sdoff = srow * 128 + ((sch ^ (srow & 7)) << 4);

    int i8 = lane & 7;
    int la = lane & 15, ca = lane >> 4;
    int rowoff = ((lane >> 4) << 3) + i8;
    int choff = (lane >> 3) & 1;
    int matq = lane >> 3;
    int vrowb = (((matq & 1) << 3) + i8) * 128;
    int chh = matq >> 1;

    // ---- prologue: Q + K/V stage0 via cp.async ----
    {
        const char* Qsrc = (const char*)(Qb + (size_t)q0 * 64);
        const char* Ksrc = (const char*)Kb;
        const char* Vsrc = (const char*)Vb;
#pragma unroll
        for (int i = 0; i < 4; ++i) {
            CP16(smb + 32768 + sdoff + i * 2048, Qsrc + sgoff + i * 2048);
            CP16(smb + sdoff + i * 2048,         Ksrc + sgoff + i * 2048);
            CP16(smb + 8192 + sdoff + i * 2048,  Vsrc + sgoff + i * 2048);
        }
        asm volatile("cp.async.commit_group;");
        asm volatile("cp.async.wait_group 0;" ::: "memory");
    }
    __syncthreads();

    unsigned qa[4][4];
    {
        int qrow = w * 16 + la;
#pragma unroll
        for (int s = 0; s < 4; ++s)
            ldsm4(qa[s][0], qa[s][1], qa[s][2], qa[s][3],
                  smb + 32768 + qrow * 128 + ((((2 * s + ca)) ^ (qrow & 7)) << 4));
    }

    float accO[8][4];
#pragma unroll
    for (int ot = 0; ot < 8; ++ot)
#pragma unroll
        for (int i = 0; i < 4; ++i) accO[ot][i] = 0.f;
    float m0 = -1e30f, m1 = -1e30f, l0 = 0.f, l1 = 0.f;

    const __half* G0 = g_G + ((size_t)bz * Nn + (q0 + w * 16 + g)) * Nn;
    const __half* G1 = G0 + (size_t)8 * Nn;
    const float SL2 = SCALE_F * LOG2E;

    for (int kt = 0; kt < 32; ++kt) {
        unsigned kb = smb + (kt & 1) * 16384;
        unsigned vb = kb + 8192;

        if (kt < 31) {
            unsigned kbN = smb + ((kt + 1) & 1) * 16384;
            const char* Kn = (const char*)(Kb + (size_t)(kt + 1) * 4096);
            const char* Vn = (const char*)(Vb + (size_t)(kt + 1) * 4096);
#pragma unroll
            for (int i = 0; i < 4; ++i) {
                CP16(kbN + sdoff + i * 2048,        Kn + sgoff + i * 2048);
                CP16(kbN + 8192 + sdoff + i * 2048, Vn + sgoff + i * 2048);
            }
            asm volatile("cp.async.commit_group;");
        }

        // gate prefetch as fp16 pairs (consumed after QK)
        __half2 gA[8], gB[8];
        {
            int cbase = kt * 64 + 2 * tg;
#pragma unroll
            for (int nt = 0; nt < 8; ++nt) {
                gA[nt] = *reinterpret_cast<const __half2*>(G0 + cbase + nt * 8);
                gB[nt] = *reinterpret_cast<const __half2*>(G1 + cbase + nt * 8);
            }
        }

        // ---- S = Q K^T ----
        float sacc[8][4];
#pragma unroll
        for (int nt = 0; nt < 8; ++nt)
#pragma unroll
            for (int i = 0; i < 4; ++i) sacc[nt][i] = 0.f;
#pragma unroll
        for (int s = 0; s < 4; ++s) {
#pragma unroll
            for (int ntp = 0; ntp < 4; ++ntp) {
                unsigned b0, b1, b2, b3;
                unsigned addr = kb + (unsigned)((16 * ntp + rowoff) * 128
                                + (((2 * s + choff) ^ i8) << 4));
                ldsm4(b0, b1, b2, b3, addr);
                mma_f16(sacc[2 * ntp][0], sacc[2 * ntp][1], sacc[2 * ntp][2], sacc[2 * ntp][3],
                        qa[s][0], qa[s][1], qa[s][2], qa[s][3], b0, b1);
                mma_f16(sacc[2 * ntp + 1][0], sacc[2 * ntp + 1][1], sacc[2 * ntp + 1][2], sacc[2 * ntp + 1][3],
                        qa[s][0], qa[s][1], qa[s][2], qa[s][3], b2, b3);
            }
        }

        // logits: t = S*scale*log2e + log2(gate)
#pragma unroll
        for (int nt = 0; nt < 8; ++nt) {
            float2 ga = __half22float2(gA[nt]);
            float2 gb2 = __half22float2(gB[nt]);
            sacc[nt][0] = sacc[nt][0] * SL2 + ga.x;
            sacc[nt][1] = sacc[nt][1] * SL2 + ga.y;
            sacc[nt][2] = sacc[nt][2] * SL2 + gb2.x;
            sacc[nt][3] = sacc[nt][3] * SL2 + gb2.y;
        }

        // online softmax
        float mn0 = m0, mn1 = m1;
#pragma unroll
        for (int nt = 0; nt < 8; ++nt) {
            mn0 = fmaxf(mn0, fmaxf(sacc[nt][0], sacc[nt][1]));
            mn1 = fmaxf(mn1, fmaxf(sacc[nt][2], sacc[nt][3]));
        }
        mn0 = fmaxf(mn0, __shfl_xor_sync(0xffffffffu, mn0, 1));
        mn0 = fmaxf(mn0, __shfl_xor_sync(0xffffffffu, mn0, 2));
        mn1 = fmaxf(mn1, __shfl_xor_sync(0xffffffffu, mn1, 1));
        mn1 = fmaxf(mn1, __shfl_xor_sync(0xffffffffu, mn1, 2));
        float al0 = exp2f(m0 - mn0), al1 = exp2f(m1 - mn1);
        m0 = mn0; m1 = mn1;
        l0 *= al0; l1 *= al1;
#pragma unroll
        for (int ot = 0; ot < 8; ++ot) {
            accO[ot][0] *= al0; accO[ot][1] *= al0;
            accO[ot][2] *= al1; accO[ot][3] *= al1;
        }

        // P = exp2(t - m); accumulate l
#pragma unroll
        for (int nt = 0; nt < 8; ++nt) {
            sacc[nt][0] = exp2f(sacc[nt][0] - m0);
            sacc[nt][1] = exp2f(sacc[nt][1] - m0);
            sacc[nt][2] = exp2f(sacc[nt][2] - m1);
            sacc[nt][3] = exp2f(sacc[nt][3] - m1);
            l0 += sacc[nt][0] + sacc[nt][1];
            l1 += sacc[nt][2] + sacc[nt][3];
        }

        // ---- O += P@V ----
#pragma unroll
        for (int s = 0; s < 4; ++s) {
            unsigned aP0 = pack2(sacc[2 * s][0],     sacc[2 * s][1]);
            unsigned aP1 = pack2(sacc[2 * s][2],     sacc[2 * s][3]);
            unsigned aP2 = pack2(sacc[2 * s + 1][0], sacc[2 * s + 1][1]);
            unsigned aP3 = pack2(sacc[2 * s + 1][2], sacc[2 * s + 1][3]);
            unsigned base_s = vb + s * 2048 + vrowb;
#pragma unroll
            for (int otp = 0; otp < 4; ++otp) {
                unsigned b0, b1, b2, b3;
                ldsm4t(b0, b1, b2, b3, base_s + ((((2 * otp + chh) ^ i8)) << 4));
                mma_f16(accO[2 * otp][0], accO[2 * otp][1], accO[2 * otp][2], accO[2 * otp][3],
                        aP0, aP1, aP2, aP3, b0, b1);
                mma_f16(accO[2 * otp + 1][0], accO[2 * otp + 1][1], accO[2 * otp + 1][2], accO[2 * otp + 1][3],
                        aP0, aP1, aP2, aP3, b2, b3);
            }
        }

        if (kt < 31)
            asm volatile("cp.async.wait_group 0;" ::: "memory");
        __syncthreads();
    }

    // quad-reduce denominators
    l0 += __shfl_xor_sync(0xffffffffu, l0, 1);
    l0 += __shfl_xor_sync(0xffffffffu, l0, 2);
    l1 += __shfl_xor_sync(0xffffffffu, l1, 1);
    l1 += __shfl_xor_sync(0xffffffffu, l1, 2);

    float inv0 = 1.0f / l0, inv1 = 1.0f / l1;
    int qr0 = q0 + w * 16 + g, qr1 = qr0 + 8;
    __half* O0 = g_AO + ((size_t)(bz * Nn + qr0)) * DM + h * 64;
    __half* O1 = g_AO + ((size_t)(bz * Nn + qr1)) * DM + h * 64;
#pragma unroll
    for (int ot = 0; ot < 8; ++ot) {
        int d = ot * 8 + 2 * tg;
        *reinterpret_cast<__half2*>(O0 + d) = __floats2half2_rn(accO[ot][0] * inv0, accO[ot][1] * inv0);
        *reinterpret_cast<__half2*>(O1 + d) = __floats2half2_rn(accO[ot][2] * inv1, accO[ot][3] * inv1);
    }
}

// ============================================================
extern "C" void kernel_launch(void* const* d_in, const int* in_sizes, int n_in,
                              void* d_out, int out_size) {
    const float* Qin  = (const float*)d_in[0];
    const float* KVin = (const float*)d_in[1];
    const float* SC   = (const float*)d_in[2];
    const float* Wq   = (const float*)d_in[3];
    const float* Wqb  = (const float*)d_in[4];
    const float* Wk   = (const float*)d_in[5];
    const float* Wkb  = (const float*)d_in[6];
    const float* Wv   = (const float*)d_in[7];
    const float* Wvb  = (const float*)d_in[8];
    const float* gw   = (const float*)d_in[9];
    const float* gb   = (const float*)d_in[10];
    const float* Wo   = (const float*)d_in[11];
    const float* Wob  = (const float*)d_in[12];
    float* out = (float*)d_out;

    cudaFuncSetAttribute(gemm_h,       cudaFuncAttributeMaxDynamicSharedMemorySize, GEMMH_SMEM);
    cudaFuncSetAttribute(flash_kernel, cudaFuncAttributeMaxDynamicSharedMemorySize, FLASH_SMEM);

    // fused one-time fp16 conversions (weights + both inputs)
    cvt_all<<<9216, 256>>>(reinterpret_cast<const float4*>(Wq),
                           reinterpret_cast<const float4*>(Wk),
                           reinterpret_cast<const float4*>(Wv),
                           reinterpret_cast<const float4*>(Wo),
                           reinterpret_cast<const float4*>(Qin),
                           reinterpret_cast<const float4*>(KVin));

    gate_kernel<<<16384, 256>>>(reinterpret_cast<const float4*>(SC), gw, gb);

    gemm_h<<<dim3(8, 64),  256, GEMMH_SMEM>>>(Wqb, nullptr, nullptr, 0, 0);
    gemm_h<<<dim3(16, 64), 256, GEMMH_SMEM>>>(Wkb, Wvb,     nullptr, 1, 4);

    flash_kernel<<<dim3(8, 32, 4), 128, FLASH_SMEM>>>();

    gemm_h<<<dim3(8, 64),  256, GEMMH_SMEM>>>(Wob, nullptr, out, 2, 3);
}

// round 15
// speedup vs baseline: 3.2917x; 1.0253x over previous
#include <cuda_runtime.h>
#include <cuda_fp16.h>
#include <cstdint>

#define Bb   4
#define Nn   2048
#define DM   512
#define Hh   8
#define DH   64
#define SCALE_F 0.125f
#define LOG2E 1.4426950408889634f

#define GEMMH_SMEM 49152   // 2 stages x (A 128x64 fp16 = 16KB + B 64x64 fp16 = 8KB)
#define FLASH_SMEM 40960   // 2 stages x (K 8KB + V 8KB) + Q 8KB

// ---- scratch (static __device__, allocation-free) ----
__device__ __half g_G [(size_t)Bb * Nn * Nn];          // log2-gate, fp16 (33.5 MB)
__device__ __half g_Qh[(size_t)Bb * Hh * Nn * DH];     // Q  [bh][n][d] fp16
__device__ __half g_K [(size_t)Bb * Hh * Nn * DH];     // K  fp16
__device__ __half g_V [(size_t)Bb * Hh * Nn * DH];     // V  fp16
__device__ __half g_AO[(size_t)Bb * Nn * DM];          // attn out fp16
__device__ __half g_Wh[(size_t)4 * DM * DM];           // Wq|Wk|Wv|Wo fp16
__device__ __half g_A0[(size_t)Bb * Nn * DM];          // Q_input fp16
__device__ __half g_A1[(size_t)Bb * Nn * DM];          // KV_input fp16

// ---- helpers ----
__device__ __forceinline__ unsigned u(float x) { return __float_as_uint(x); }
__device__ __forceinline__ unsigned pack2(float lo, float hi) {
    __half2 h = __floats2half2_rn(lo, hi);
    return *reinterpret_cast<unsigned*>(&h);
}
__device__ __forceinline__ unsigned ex2h2(unsigned x) {   // exp2 on packed fp16 pair
    unsigned r;
    asm("ex2.approx.f16x2 %0, %1;" : "=r"(r) : "r"(x));
    return r;
}

#define CP16(dst, src) \
    asm volatile("cp.async.cg.shared.global [%0], [%1], 16;" :: "r"(dst), "l"(src))

__device__ __forceinline__ void mma_f16(float& d0, float& d1, float& d2, float& d3,
                                        unsigned a0, unsigned a1, unsigned a2, unsigned a3,
                                        unsigned b0, unsigned b1) {
    asm volatile(
        "mma.sync.aligned.m16n8k16.row.col.f32.f16.f16.f32 "
        "{%0,%1,%2,%3}, {%4,%5,%6,%7}, {%8,%9}, {%0,%1,%2,%3};"
        : "+f"(d0), "+f"(d1), "+f"(d2), "+f"(d3)
        : "r"(a0), "r"(a1), "r"(a2), "r"(a3), "r"(b0), "r"(b1));
}

__device__ __forceinline__ void ldsm4(unsigned& r0, unsigned& r1, unsigned& r2, unsigned& r3,
                                      unsigned addr) {
    asm volatile("ldmatrix.sync.aligned.m8n8.x4.shared.b16 {%0,%1,%2,%3}, [%4];"
                 : "=r"(r0), "=r"(r1), "=r"(r2), "=r"(r3) : "r"(addr));
}
__device__ __forceinline__ void ldsm4t(unsigned& r0, unsigned& r1, unsigned& r2, unsigned& r3,
                                       unsigned addr) {
    asm volatile("ldmatrix.sync.aligned.m8n8.x4.trans.shared.b16 {%0,%1,%2,%3}, [%4];"
                 : "=r"(r0), "=r"(r1), "=r"(r2), "=r"(r3) : "r"(addr));
}

// ============================================================
// Kernel A: fused f32 -> fp16 convert for ALL weights + inputs.
// ============================================================
__global__ void cvt_all(const float4* __restrict__ Wq, const float4* __restrict__ Wk,
                        const float4* __restrict__ Wv, const float4* __restrict__ Wo,
                        const float4* __restrict__ Qin, const float4* __restrict__ KVin) {
    int b = blockIdx.x;
    const float4* src;
    uint2* dst;
    int i;
    if (b < 1024) {
        int seg = b >> 8;
        i = (b & 255) * 256 + threadIdx.x;
        src = (seg == 0) ? Wq : (seg == 1) ? Wk : (seg == 2) ? Wv : Wo;
        dst = reinterpret_cast<uint2*>(g_Wh) + seg * 65536;
    } else if (b < 5120) {
        i = (b - 1024) * 256 + threadIdx.x;
        src = Qin;  dst = reinterpret_cast<uint2*>(g_A0);
    } else {
        i = (b - 5120) * 256 + threadIdx.x;
        src = KVin; dst = reinterpret_cast<uint2*>(g_A1);
    }
    float4 v = src[i];
    uint2 o;
    o.x = pack2(v.x, v.y);
    o.y = pack2(v.z, v.w);
    dst[i] = o;
}

// ============================================================
// Kernel 0: gate precompute  G = (half) log2(sigmoid(w*SC + b) + 1e-8)
// ============================================================
__global__ void gate_kernel(const float4* __restrict__ SC,
                            const float* __restrict__ gw,
                            const float* __restrict__ gb) {
    int i = blockIdx.x * 256 + threadIdx.x;
    float w = __ldg(gw), b = __ldg(gb);
    float4 s = SC[i];
    float rx = __log2f(__fdividef(1.f, 1.f + __expf(-(s.x * w + b))) + 1e-8f);
    float ry = __log2f(__fdividef(1.f, 1.f + __expf(-(s.y * w + b))) + 1e-8f);
    float rz = __log2f(__fdividef(1.f, 1.f + __expf(-(s.z * w + b))) + 1e-8f);
    float rw = __log2f(__fdividef(1.f, 1.f + __expf(-(s.w * w + b))) + 1e-8f);
    uint2 o;
    o.x = pack2(rx, ry);
    o.y = pack2(rz, rw);
    reinterpret_cast<uint2*>(g_G)[i] = o;
}

// ============================================================
// Kernel 1: fp16 GEMM  C[8192,512] = A @ W^T + bias
//  (R14 core; MMA loop reordered s-outer for longer dep chains)
// ============================================================
__global__ __launch_bounds__(256, 2) void gemm_h(const float* __restrict__ biasa,
                                                 const float* __restrict__ biasb,
                                                 float* __restrict__ Cext,
                                                 int amode, int cmode) {
    extern __shared__ char smc[];
    unsigned smb;
    asm("{ .reg .u64 t; cvta.to.shared.u64 t, %1; cvt.u32.u64 %0, t; }"
        : "=r"(smb) : "l"(smc));

    const __half* A = (amode == 0) ? g_A0 : (amode == 1 ? g_A1 : g_AO);
    const __half* W;
    const float* bias;
    if (cmode == 0)      { W = g_Wh;                bias = biasa; }
    else if (cmode == 3) { W = g_Wh + 3 * DM * DM;  bias = biasa; }
    else {
        if (blockIdx.x >= 8) { W = g_Wh + 2 * DM * DM; bias = biasb; }
        else                 { W = g_Wh + 1 * DM * DM; bias = biasa; }
    }

    int tid  = threadIdx.x;
    int warp = tid >> 5, lane = tid & 31;
    int g = lane >> 2, tg = lane & 3;
    int wm = warp >> 1, wn = warp & 1;
    int mbase = blockIdx.y * 128, nbase = (blockIdx.x & 7) * 64;

    int srow = tid >> 3, sch = tid & 7;
    int sdoff = ((sch ^ (srow & 7)) << 4);

    int i8 = lane & 7;
    int la = lane & 15, ca = lane >> 4;
    int rowoffB = ((lane >> 4) << 3) + i8;
    int choffB  = (lane >> 3) & 1;

    float acc[2][4][4];
#pragma unroll
    for (int mt = 0; mt < 2; ++mt)
#pragma unroll
        for (int nt = 0; nt < 4; ++nt)
#pragma unroll
            for (int i = 0; i < 4; ++i) acc[mt][nt][i] = 0.f;

    {
#pragma unroll
        for (int i = 0; i < 4; ++i) {
            int r = srow + 32 * i;
            CP16(smb + r * 128 + sdoff,
                 (const char*)(A + (size_t)(mbase + r) * 512) + sch * 16);
        }
#pragma unroll
        for (int i = 0; i < 2; ++i) {
            int r = srow + 32 * i;
            CP16(smb + 16384 + r * 128 + sdoff,
                 (const char*)(W + (size_t)(nbase + r) * 512) + sch * 16);
        }
        asm volatile("cp.async.commit_group;");
        asm volatile("cp.async.wait_group 0;" ::: "memory");
    }
    __syncthreads();

    for (int kt = 0; kt < 8; ++kt) {
        unsigned Ab = smb + (kt & 1) * 24576;
        unsigned Bsm = Ab + 16384;

        if (kt < 7) {
            unsigned AbN = smb + ((kt + 1) & 1) * 24576;
            int kh = (kt + 1) * 64;
#pragma unroll
            for (int i = 0; i < 4; ++i) {
                int r = srow + 32 * i;
                CP16(AbN + r * 128 + sdoff,
                     (const char*)(A + (size_t)(mbase + r) * 512 + kh) + sch * 16);
            }
#pragma unroll
            for (int i = 0; i < 2; ++i) {
                int r = srow + 32 * i;
                CP16(AbN + 16384 + r * 128 + sdoff,
                     (const char*)(W + (size_t)(nbase + r) * 512 + kh) + sch * 16);
            }
            asm volatile("cp.async.commit_group;");
        }

        unsigned af[2][4][4];
#pragma unroll
        for (int mt = 0; mt < 2; ++mt) {
            int row = wm * 32 + mt * 16 + la;
#pragma unroll
            for (int s = 0; s < 4; ++s)
                ldsm4(af[mt][s][0], af[mt][s][1], af[mt][s][2], af[mt][s][3],
                      Ab + row * 128 + ((((2 * s + ca)) ^ (row & 7)) << 4));
        }

        // s-outer: both ntp groups per s -> 8 indep MMA chains per acc reuse
#pragma unroll
        for (int s = 0; s < 4; ++s) {
            unsigned bf[2][4];
#pragma unroll
            for (int ntp = 0; ntp < 2; ++ntp) {
                int rowb = wn * 32 + ntp * 16 + rowoffB;
                ldsm4(bf[ntp][0], bf[ntp][1], bf[ntp][2], bf[ntp][3],
                      Bsm + rowb * 128 + ((((2 * s + choffB)) ^ (rowb & 7)) << 4));
            }
#pragma unroll
            for (int ntp = 0; ntp < 2; ++ntp) {
#pragma unroll
                for (int mt = 0; mt < 2; ++mt) {
                    mma_f16(acc[mt][2 * ntp][0], acc[mt][2 * ntp][1],
                            acc[mt][2 * ntp][2], acc[mt][2 * ntp][3],
                            af[mt][s][0], af[mt][s][1], af[mt][s][2], af[mt][s][3],
                            bf[ntp][0], bf[ntp][1]);
                    mma_f16(acc[mt][2 * ntp + 1][0], acc[mt][2 * ntp + 1][1],
                            acc[mt][2 * ntp + 1][2], acc[mt][2 * ntp + 1][3],
                            af[mt][s][0], af[mt][s][1], af[mt][s][2], af[mt][s][3],
                            bf[ntp][2], bf[ntp][3]);
                }
            }
        }

        if (kt < 7)
            asm volatile("cp.async.wait_group 0;" ::: "memory");
        __syncthreads();
    }

#pragma unroll
    for (int mt = 0; mt < 2; ++mt)
#pragma unroll
        for (int nt = 0; nt < 4; ++nt) {
            int col = nbase + wn * 32 + nt * 8 + 2 * tg;
            float b0 = bias[col], b1 = bias[col + 1];
            int r0 = mbase + wm * 32 + mt * 16 + g;
            int r1 = r0 + 8;
            float v00 = acc[mt][nt][0] + b0, v01 = acc[mt][nt][1] + b1;
            float v10 = acc[mt][nt][2] + b0, v11 = acc[mt][nt][3] + b1;
            if (cmode == 3) {
                *reinterpret_cast<float2*>(Cext + (size_t)r0 * 512 + col) = make_float2(v00, v01);
                *reinterpret_cast<float2*>(Cext + (size_t)r1 * 512 + col) = make_float2(v10, v11);
            } else {
                __half* Ch = (cmode == 0) ? g_Qh : ((blockIdx.x >= 8) ? g_V : g_K);
                int h = col >> 6, d = col & 63;
                {
                    int b = r0 >> 11, n = r0 & 2047;
                    __half* p = Ch + (size_t)(((b << 3) + h) * 2048 + n) * 64 + d;
                    *reinterpret_cast<__half2*>(p) = __floats2half2_rn(v00, v01);
                }
                {
                    int b = r1 >> 11, n = r1 & 2047;
                    __half* p = Ch + (size_t)(((b << 3) + h) * 2048 + n) * 64 + d;
                    *reinterpret_cast<__half2*>(p) = __floats2half2_rn(v10, v11);
                }
            }
        }
}

// ============================================================
// Kernel 2: fp16 flash attention.
//  R14 core + (a) P via ex2.approx.f16x2 (outputs ARE the PV A-frags),
//  (b) softmax denominator via ones-B MMA (no scalar l adds, no final
//  quad shuffles; lacc rescaled alongside accO).
// ============================================================
__global__ __launch_bounds__(128, 3) void flash_kernel() {
    extern __shared__ char smc[];
    unsigned smb;
    asm("{ .reg .u64 t; cvta.to.shared.u64 t, %1; cvt.u32.u64 %0, t; }"
        : "=r"(smb) : "l"(smc));

    int tid = threadIdx.x, w = tid >> 5, lane = tid & 31;
    int g = lane >> 2, tg = lane & 3;
    int h = blockIdx.x, qt = blockIdx.y, bz = blockIdx.z;
    int bh = bz * 8 + h;
    const __half* Qb = g_Qh + (size_t)bh * Nn * DH;
    const __half* Kb = g_K  + (size_t)bh * Nn * DH;
    const __half* Vb = g_V  + (size_t)bh * Nn * DH;
    int q0 = qt * 64;

    int srow = tid >> 3, sch = tid & 7;
    int sgoff = srow * 128 + sch * 16;
    int sdoff = srow * 128 + ((sch ^ (srow & 7)) << 4);

    int i8 = lane & 7;
    int la = lane & 15, ca = lane >> 4;
    int rowoff = ((lane >> 4) << 3) + i8;
    int choff = (lane >> 3) & 1;
    int matq = lane >> 3;
    int vrowb = (((matq & 1) << 3) + i8) * 128;
    int chh = matq >> 1;

    // ---- prologue: Q + K/V stage0 via cp.async ----
    {
        const char* Qsrc = (const char*)(Qb + (size_t)q0 * 64);
        const char* Ksrc = (const char*)Kb;
        const char* Vsrc = (const char*)Vb;
#pragma unroll
        for (int i = 0; i < 4; ++i) {
            CP16(smb + 32768 + sdoff + i * 2048, Qsrc + sgoff + i * 2048);
            CP16(smb + sdoff + i * 2048,         Ksrc + sgoff + i * 2048);
            CP16(smb + 8192 + sdoff + i * 2048,  Vsrc + sgoff + i * 2048);
        }
        asm volatile("cp.async.commit_group;");
        asm volatile("cp.async.wait_group 0;" ::: "memory");
    }
    __syncthreads();

    unsigned qa[4][4];
    {
        int qrow = w * 16 + la;
#pragma unroll
        for (int s = 0; s < 4; ++s)
            ldsm4(qa[s][0], qa[s][1], qa[s][2], qa[s][3],
                  smb + 32768 + qrow * 128 + ((((2 * s + ca)) ^ (qrow & 7)) << 4));
    }

    float accO[8][4];
#pragma unroll
    for (int ot = 0; ot < 8; ++ot)
#pragma unroll
        for (int i = 0; i < 4; ++i) accO[ot][i] = 0.f;
    float lacc[4] = {0.f, 0.f, 0.f, 0.f};
    float m0 = -1e30f, m1 = -1e30f;

    const __half* G0 = g_G + ((size_t)bz * Nn + (q0 + w * 16 + g)) * Nn;
    const __half* G1 = G0 + (size_t)8 * Nn;
    const float SL2 = SCALE_F * LOG2E;
    const unsigned ONES = 0x3C003C00u;   // (1.0h, 1.0h)

    for (int kt = 0; kt < 32; ++kt) {
        unsigned kb = smb + (kt & 1) * 16384;
        unsigned vb = kb + 8192;

        if (kt < 31) {
            unsigned kbN = smb + ((kt + 1) & 1) * 16384;
            const char* Kn = (const char*)(Kb + (size_t)(kt + 1) * 4096);
            const char* Vn = (const char*)(Vb + (size_t)(kt + 1) * 4096);
#pragma unroll
            for (int i = 0; i < 4; ++i) {
                CP16(kbN + sdoff + i * 2048,        Kn + sgoff + i * 2048);
                CP16(kbN + 8192 + sdoff + i * 2048, Vn + sgoff + i * 2048);
            }
            asm volatile("cp.async.commit_group;");
        }

        // gate prefetch as fp16 pairs (consumed after QK)
        __half2 gA[8], gB[8];
        {
            int cbase = kt * 64 + 2 * tg;
#pragma unroll
            for (int nt = 0; nt < 8; ++nt) {
                gA[nt] = *reinterpret_cast<const __half2*>(G0 + cbase + nt * 8);
                gB[nt] = *reinterpret_cast<const __half2*>(G1 + cbase + nt * 8);
            }
        }

        // ---- S = Q K^T ----
        float sacc[8][4];
#pragma unroll
        for (int nt = 0; nt < 8; ++nt)
#pragma unroll
            for (int i = 0; i < 4; ++i) sacc[nt][i] = 0.f;
#pragma unroll
        for (int s = 0; s < 4; ++s) {
#pragma unroll
            for (int ntp = 0; ntp < 4; ++ntp) {
                unsigned b0, b1, b2, b3;
                unsigned addr = kb + (unsigned)((16 * ntp + rowoff) * 128
                                + (((2 * s + choff) ^ i8) << 4));
                ldsm4(b0, b1, b2, b3, addr);
                mma_f16(sacc[2 * ntp][0], sacc[2 * ntp][1], sacc[2 * ntp][2], sacc[2 * ntp][3],
                        qa[s][0], qa[s][1], qa[s][2], qa[s][3], b0, b1);
                mma_f16(sacc[2 * ntp + 1][0], sacc[2 * ntp + 1][1], sacc[2 * ntp + 1][2], sacc[2 * ntp + 1][3],
                        qa[s][0], qa[s][1], qa[s][2], qa[s][3], b2, b3);
            }
        }

        // logits: t = S*scale*log2e + log2(gate)
#pragma unroll
        for (int nt = 0; nt < 8; ++nt) {
            float2 ga = __half22float2(gA[nt]);
            float2 gb2 = __half22float2(gB[nt]);
            sacc[nt][0] = sacc[nt][0] * SL2 + ga.x;
            sacc[nt][1] = sacc[nt][1] * SL2 + ga.y;
            sacc[nt][2] = sacc[nt][2] * SL2 + gb2.x;
            sacc[nt][3] = sacc[nt][3] * SL2 + gb2.y;
        }

        // online softmax max update
        float mn0 = m0, mn1 = m1;
#pragma unroll
        for (int nt = 0; nt < 8; ++nt) {
            mn0 = fmaxf(mn0, fmaxf(sacc[nt][0], sacc[nt][1]));
            mn1 = fmaxf(mn1, fmaxf(sacc[nt][2], sacc[nt][3]));
        }
        mn0 = fmaxf(mn0, __shfl_xor_sync(0xffffffffu, mn0, 1));
        mn0 = fmaxf(mn0, __shfl_xor_sync(0xffffffffu, mn0, 2));
        mn1 = fmaxf(mn1, __shfl_xor_sync(0xffffffffu, mn1, 1));
        mn1 = fmaxf(mn1, __shfl_xor_sync(0xffffffffu, mn1, 2));
        float al0 = exp2f(m0 - mn0), al1 = exp2f(m1 - mn1);
        m0 = mn0; m1 = mn1;
#pragma unroll
        for (int ot = 0; ot < 8; ++ot) {
            accO[ot][0] *= al0; accO[ot][1] *= al0;
            accO[ot][2] *= al1; accO[ot][3] *= al1;
        }
        lacc[0] *= al0; lacc[1] *= al0;
        lacc[2] *= al1; lacc[3] *= al1;

        // P = exp2(t - m) directly in fp16 pairs (these ARE the PV A-frags)
        unsigned pe[8], po[8];
#pragma unroll
        for (int nt = 0; nt < 8; ++nt) {
            pe[nt] = ex2h2(pack2(sacc[nt][0] - m0, sacc[nt][1] - m0));
            po[nt] = ex2h2(pack2(sacc[nt][2] - m1, sacc[nt][3] - m1));
        }

        // ---- O += P@V ; l += P@ones ----
#pragma unroll
        for (int s = 0; s < 4; ++s) {
            unsigned aP0 = pe[2 * s];
            unsigned aP1 = po[2 * s];
            unsigned aP2 = pe[2 * s + 1];
            unsigned aP3 = po[2 * s + 1];
            mma_f16(lacc[0], lacc[1], lacc[2], lacc[3],
                    aP0, aP1, aP2, aP3, ONES, ONES);
            unsigned base_s = vb + s * 2048 + vrowb;
#pragma unroll
            for (int otp = 0; otp < 4; ++otp) {
                unsigned b0, b1, b2, b3;
                ldsm4t(b0, b1, b2, b3, base_s + ((((2 * otp + chh) ^ i8)) << 4));
                mma_f16(accO[2 * otp][0], accO[2 * otp][1], accO[2 * otp][2], accO[2 * otp][3],
                        aP0, aP1, aP2, aP3, b0, b1);
                mma_f16(accO[2 * otp + 1][0], accO[2 * otp + 1][1], accO[2 * otp + 1][2], accO[2 * otp + 1][3],
                        aP0, aP1, aP2, aP3, b2, b3);
            }
        }

        if (kt < 31)
            asm volatile("cp.async.wait_group 0;" ::: "memory");
        __syncthreads();
    }

    // lacc[0] = full row-g denominator, lacc[2] = row g+8 (ones-B makes all
    // columns equal, so every quad lane already holds the complete sum).
    float inv0 = 1.0f / lacc[0], inv1 = 1.0f / lacc[2];
    int qr0 = q0 + w * 16 + g, qr1 = qr0 + 8;
    __half* O0 = g_AO + ((size_t)(bz * Nn + qr0)) * DM + h * 64;
    __half* O1 = g_AO + ((size_t)(bz * Nn + qr1)) * DM + h * 64;
#pragma unroll
    for (int ot = 0; ot < 8; ++ot) {
        int d = ot * 8 + 2 * tg;
        *reinterpret_cast<__half2*>(O0 + d) = __floats2half2_rn(accO[ot][0] * inv0, accO[ot][1] * inv0);
        *reinterpret_cast<__half2*>(O1 + d) = __floats2half2_rn(accO[ot][2] * inv1, accO[ot][3] * inv1);
    }
}

// ============================================================
extern "C" void kernel_launch(void* const* d_in, const int* in_sizes, int n_in,
                              void* d_out, int out_size) {
    const float* Qin  = (const float*)d_in[0];
    const float* KVin = (const float*)d_in[1];
    const float* SC   = (const float*)d_in[2];
    const float* Wq   = (const float*)d_in[3];
    const float* Wqb  = (const float*)d_in[4];
    const float* Wk   = (const float*)d_in[5];
    const float* Wkb  = (const float*)d_in[6];
    const float* Wv   = (const float*)d_in[7];
    const float* Wvb  = (const float*)d_in[8];
    const float* gw   = (const float*)d_in[9];
    const float* gb   = (const float*)d_in[10];
    const float* Wo   = (const float*)d_in[11];
    const float* Wob  = (const float*)d_in[12];
    float* out = (float*)d_out;

    cudaFuncSetAttribute(gemm_h,       cudaFuncAttributeMaxDynamicSharedMemorySize, GEMMH_SMEM);
    cudaFuncSetAttribute(flash_kernel, cudaFuncAttributeMaxDynamicSharedMemorySize, FLASH_SMEM);

    cvt_all<<<9216, 256>>>(reinterpret_cast<const float4*>(Wq),
                           reinterpret_cast<const float4*>(Wk),
                           reinterpret_cast<const float4*>(Wv),
                           reinterpret_cast<const float4*>(Wo),
                           reinterpret_cast<const float4*>(Qin),
                           reinterpret_cast<const float4*>(KVin));

    gate_kernel<<<16384, 256>>>(reinterpret_cast<const float4*>(SC), gw, gb);

    gemm_h<<<dim3(8, 64),  256, GEMMH_SMEM>>>(Wqb, nullptr, nullptr, 0, 0);
    gemm_h<<<dim3(16, 64), 256, GEMMH_SMEM>>>(Wkb, Wvb,     nullptr, 1, 4);

    flash_kernel<<<dim3(8, 32, 4), 128, FLASH_SMEM>>>();

    gemm_h<<<dim3(8, 64),  256, GEMMH_SMEM>>>(Wob, nullptr, out, 2, 3);
}

// round 16
// speedup vs baseline: 3.4183x; 1.0385x over previous
#include <cuda_runtime.h>
#include <cuda_fp16.h>
#include <cstdint>

#define Bb   4
#define Nn   2048
#define DM   512
#define Hh   8
#define DH   64
#define SCALE_F 0.125f
#define LOG2E 1.4426950408889634f

#define GEMMH_SMEM 73728   // 3 stages x (A 128x64 fp16 = 16KB + B 64x64 fp16 = 8KB)
#define FLASH_SMEM 40960   // 2 stages x (K 8KB + V 8KB) + Q 8KB

// ---- scratch (static __device__, allocation-free) ----
__device__ __half g_G [(size_t)Bb * Nn * Nn];          // log2-gate, fp16 (33.5 MB)
__device__ __half g_Qh[(size_t)Bb * Hh * Nn * DH];     // Q  [bh][n][d] fp16
__device__ __half g_K [(size_t)Bb * Hh * Nn * DH];     // K  fp16
__device__ __half g_V [(size_t)Bb * Hh * Nn * DH];     // V  fp16
__device__ __half g_AO[(size_t)Bb * Nn * DM];          // attn out fp16
__device__ __half g_Wh[(size_t)4 * DM * DM];           // Wq|Wk|Wv|Wo fp16
__device__ __half g_A0[(size_t)Bb * Nn * DM];          // Q_input fp16
__device__ __half g_A1[(size_t)Bb * Nn * DM];          // KV_input fp16

// ---- helpers ----
__device__ __forceinline__ unsigned u(float x) { return __float_as_uint(x); }
__device__ __forceinline__ unsigned pack2(float lo, float hi) {
    __half2 h = __floats2half2_rn(lo, hi);
    return *reinterpret_cast<unsigned*>(&h);
}
__device__ __forceinline__ unsigned ex2h2(unsigned x) {   // exp2 on packed fp16 pair
    unsigned r;
    asm("ex2.approx.f16x2 %0, %1;" : "=r"(r) : "r"(x));
    return r;
}

#define CP16(dst, src) \
    asm volatile("cp.async.cg.shared.global [%0], [%1], 16;" :: "r"(dst), "l"(src))

__device__ __forceinline__ void mma_f16(float& d0, float& d1, float& d2, float& d3,
                                        unsigned a0, unsigned a1, unsigned a2, unsigned a3,
                                        unsigned b0, unsigned b1) {
    asm volatile(
        "mma.sync.aligned.m16n8k16.row.col.f32.f16.f16.f32 "
        "{%0,%1,%2,%3}, {%4,%5,%6,%7}, {%8,%9}, {%0,%1,%2,%3};"
        : "+f"(d0), "+f"(d1), "+f"(d2), "+f"(d3)
        : "r"(a0), "r"(a1), "r"(a2), "r"(a3), "r"(b0), "r"(b1));
}

__device__ __forceinline__ void ldsm4(unsigned& r0, unsigned& r1, unsigned& r2, unsigned& r3,
                                      unsigned addr) {
    asm volatile("ldmatrix.sync.aligned.m8n8.x4.shared.b16 {%0,%1,%2,%3}, [%4];"
                 : "=r"(r0), "=r"(r1), "=r"(r2), "=r"(r3) : "r"(addr));
}
__device__ __forceinline__ void ldsm4t(unsigned& r0, unsigned& r1, unsigned& r2, unsigned& r3,
                                       unsigned addr) {
    asm volatile("ldmatrix.sync.aligned.m8n8.x4.trans.shared.b16 {%0,%1,%2,%3}, [%4];"
                 : "=r"(r0), "=r"(r1), "=r"(r2), "=r"(r3) : "r"(addr));
}

// ============================================================
// Kernel A: fused f32->fp16 converts AND gate precompute, one launch.
//  blocks [0,1024): Wq|Wk|Wv|Wo -> g_Wh
//  blocks [1024,5120): Qin -> g_A0 ; [5120,9216): KVin -> g_A1
//  blocks [9216,25600): gate  G = (half) log2(sigmoid(w*SC+b)+1e-8)
// ============================================================
__global__ void prep_all(const float4* __restrict__ Wq, const float4* __restrict__ Wk,
                         const float4* __restrict__ Wv, const float4* __restrict__ Wo,
                         const float4* __restrict__ Qin, const float4* __restrict__ KVin,
                         const float4* __restrict__ SC,
                         const float* __restrict__ gw, const float* __restrict__ gb) {
    int b = blockIdx.x;
    if (b >= 9216) {
        int i = (b - 9216) * 256 + threadIdx.x;
        float w = __ldg(gw), bia = __ldg(gb);
        float4 s = SC[i];
        float rx = __log2f(__fdividef(1.f, 1.f + __expf(-(s.x * w + bia))) + 1e-8f);
        float ry = __log2f(__fdividef(1.f, 1.f + __expf(-(s.y * w + bia))) + 1e-8f);
        float rz = __log2f(__fdividef(1.f, 1.f + __expf(-(s.z * w + bia))) + 1e-8f);
        float rw = __log2f(__fdividef(1.f, 1.f + __expf(-(s.w * w + bia))) + 1e-8f);
        uint2 o;
        o.x = pack2(rx, ry);
        o.y = pack2(rz, rw);
        reinterpret_cast<uint2*>(g_G)[i] = o;
        return;
    }
    const float4* src;
    uint2* dst;
    int i;
    if (b < 1024) {
        int seg = b >> 8;
        i = (b & 255) * 256 + threadIdx.x;
        src = (seg == 0) ? Wq : (seg == 1) ? Wk : (seg == 2) ? Wv : Wo;
        dst = reinterpret_cast<uint2*>(g_Wh) + seg * 65536;
    } else if (b < 5120) {
        i = (b - 1024) * 256 + threadIdx.x;
        src = Qin;  dst = reinterpret_cast<uint2*>(g_A0);
    } else {
        i = (b - 5120) * 256 + threadIdx.x;
        src = KVin; dst = reinterpret_cast<uint2*>(g_A1);
    }
    float4 v = src[i];
    uint2 o;
    o.x = pack2(v.x, v.y);
    o.y = pack2(v.z, v.w);
    dst[i] = o;
}

// ============================================================
// Kernel 1: fp16 GEMM  C[8192,512] = A @ W^T + bias
//  3-stage cp.async pipeline (wait_group 1 steady state) to hide L2
//  latency behind MMA work.  Math order identical to R15.
// ============================================================
__global__ __launch_bounds__(256, 2) void gemm_h(const float* __restrict__ biasa,
                                                 const float* __restrict__ biasb,
                                                 float* __restrict__ Cext,
                                                 int amode, int cmode) {
    extern __shared__ char smc[];
    unsigned smb;
    asm("{ .reg .u64 t; cvta.to.shared.u64 t, %1; cvt.u32.u64 %0, t; }"
        : "=r"(smb) : "l"(smc));

    const __half* A = (amode == 0) ? g_A0 : (amode == 1 ? g_A1 : g_AO);
    const __half* W;
    const float* bias;
    if (cmode == 0)      { W = g_Wh;                bias = biasa; }
    else if (cmode == 3) { W = g_Wh + 3 * DM * DM;  bias = biasa; }
    else {
        if (blockIdx.x >= 8) { W = g_Wh + 2 * DM * DM; bias = biasb; }
        else                 { W = g_Wh + 1 * DM * DM; bias = biasa; }
    }

    int tid  = threadIdx.x;
    int warp = tid >> 5, lane = tid & 31;
    int g = lane >> 2, tg = lane & 3;
    int wm = warp >> 1, wn = warp & 1;
    int mbase = blockIdx.y * 128, nbase = (blockIdx.x & 7) * 64;

    int srow = tid >> 3, sch = tid & 7;
    int sdoff = ((sch ^ (srow & 7)) << 4);

    int i8 = lane & 7;
    int la = lane & 15, ca = lane >> 4;
    int rowoffB = ((lane >> 4) << 3) + i8;
    int choffB  = (lane >> 3) & 1;

    float acc[2][4][4];
#pragma unroll
    for (int mt = 0; mt < 2; ++mt)
#pragma unroll
        for (int nt = 0; nt < 4; ++nt)
#pragma unroll
            for (int i = 0; i < 4; ++i) acc[mt][nt][i] = 0.f;

    // ---- prologue: stage kt=0 and kt=1 (separate commit groups) ----
#pragma unroll
    for (int p = 0; p < 2; ++p) {
        unsigned Sb = smb + p * 24576;
        int kh = p * 64;
#pragma unroll
        for (int i = 0; i < 4; ++i) {
            int r = srow + 32 * i;
            CP16(Sb + r * 128 + sdoff,
                 (const char*)(A + (size_t)(mbase + r) * 512 + kh) + sch * 16);
        }
#pragma unroll
        for (int i = 0; i < 2; ++i) {
            int r = srow + 32 * i;
            CP16(Sb + 16384 + r * 128 + sdoff,
                 (const char*)(W + (size_t)(nbase + r) * 512 + kh) + sch * 16);
        }
        asm volatile("cp.async.commit_group;");
    }
    asm volatile("cp.async.wait_group 1;" ::: "memory");   // kt=0 ready
    __syncthreads();

#pragma unroll
    for (int kt = 0; kt < 8; ++kt) {
        unsigned Ab = smb + (kt % 3) * 24576;
        unsigned Bsm = Ab + 16384;

        // issue kt+2 into stage (kt+2)%3
        if (kt < 6) {
            unsigned Sn = smb + ((kt + 2) % 3) * 24576;
            int kh = (kt + 2) * 64;
#pragma unroll
            for (int i = 0; i < 4; ++i) {
                int r = srow + 32 * i;
                CP16(Sn + r * 128 + sdoff,
                     (const char*)(A + (size_t)(mbase + r) * 512 + kh) + sch * 16);
            }
#pragma unroll
            for (int i = 0; i < 2; ++i) {
                int r = srow + 32 * i;
                CP16(Sn + 16384 + r * 128 + sdoff,
                     (const char*)(W + (size_t)(nbase + r) * 512 + kh) + sch * 16);
            }
            asm volatile("cp.async.commit_group;");
        }

        unsigned af[2][4][4];
#pragma unroll
        for (int mt = 0; mt < 2; ++mt) {
            int row = wm * 32 + mt * 16 + la;
#pragma unroll
            for (int s = 0; s < 4; ++s)
                ldsm4(af[mt][s][0], af[mt][s][1], af[mt][s][2], af[mt][s][3],
                      Ab + row * 128 + ((((2 * s + ca)) ^ (row & 7)) << 4));
        }

#pragma unroll
        for (int s = 0; s < 4; ++s) {
            unsigned bf[2][4];
#pragma unroll
            for (int ntp = 0; ntp < 2; ++ntp) {
                int rowb = wn * 32 + ntp * 16 + rowoffB;
                ldsm4(bf[ntp][0], bf[ntp][1], bf[ntp][2], bf[ntp][3],
                      Bsm + rowb * 128 + ((((2 * s + choffB)) ^ (rowb & 7)) << 4));
            }
#pragma unroll
            for (int ntp = 0; ntp < 2; ++ntp) {
#pragma unroll
                for (int mt = 0; mt < 2; ++mt) {
                    mma_f16(acc[mt][2 * ntp][0], acc[mt][2 * ntp][1],
                            acc[mt][2 * ntp][2], acc[mt][2 * ntp][3],
                            af[mt][s][0], af[mt][s][1], af[mt][s][2], af[mt][s][3],
                            bf[ntp][0], bf[ntp][1]);
                    mma_f16(acc[mt][2 * ntp + 1][0], acc[mt][2 * ntp + 1][1],
                            acc[mt][2 * ntp + 1][2], acc[mt][2 * ntp + 1][3],
                            af[mt][s][0], af[mt][s][1], af[mt][s][2], af[mt][s][3],
                            bf[ntp][2], bf[ntp][3]);
                }
            }
        }

        // steady state keeps one group in flight; drain fully before last tile
        if (kt < 6)
            asm volatile("cp.async.wait_group 1;" ::: "memory");
        else if (kt == 6)
            asm volatile("cp.async.wait_group 0;" ::: "memory");
        __syncthreads();
    }

#pragma unroll
    for (int mt = 0; mt < 2; ++mt)
#pragma unroll
        for (int nt = 0; nt < 4; ++nt) {
            int col = nbase + wn * 32 + nt * 8 + 2 * tg;
            float b0 = bias[col], b1 = bias[col + 1];
            int r0 = mbase + wm * 32 + mt * 16 + g;
            int r1 = r0 + 8;
            float v00 = acc[mt][nt][0] + b0, v01 = acc[mt][nt][1] + b1;
            float v10 = acc[mt][nt][2] + b0, v11 = acc[mt][nt][3] + b1;
            if (cmode == 3) {
                *reinterpret_cast<float2*>(Cext + (size_t)r0 * 512 + col) = make_float2(v00, v01);
                *reinterpret_cast<float2*>(Cext + (size_t)r1 * 512 + col) = make_float2(v10, v11);
            } else {
                __half* Ch = (cmode == 0) ? g_Qh : ((blockIdx.x >= 8) ? g_V : g_K);
                int h = col >> 6, d = col & 63;
                {
                    int b = r0 >> 11, n = r0 & 2047;
                    __half* p = Ch + (size_t)(((b << 3) + h) * 2048 + n) * 64 + d;
                    *reinterpret_cast<__half2*>(p) = __floats2half2_rn(v00, v01);
                }
                {
                    int b = r1 >> 11, n = r1 & 2047;
                    __half* p = Ch + (size_t)(((b << 3) + h) * 2048 + n) * 64 + d;
                    *reinterpret_cast<__half2*>(p) = __floats2half2_rn(v10, v11);
                }
            }
        }
}

// ============================================================
// Kernel 2: fp16 flash attention (R15 core, unchanged)
// ============================================================
__global__ __launch_bounds__(128, 3) void flash_kernel() {
    extern __shared__ char smc[];
    unsigned smb;
    asm("{ .reg .u64 t; cvta.to.shared.u64 t, %1; cvt.u32.u64 %0, t; }"
        : "=r"(smb) : "l"(smc));

    int tid = threadIdx.x, w = tid >> 5, lane = tid & 31;
    int g = lane >> 2, tg = lane & 3;
    int h = blockIdx.x, qt = blockIdx.y, bz = blockIdx.z;
    int bh = bz * 8 + h;
    const __half* Qb = g_Qh + (size_t)bh * Nn * DH;
    const __half* Kb = g_K  + (size_t)bh * Nn * DH;
    const __half* Vb = g_V  + (size_t)bh * Nn * DH;
    int q0 = qt * 64;

    int srow = tid >> 3, sch = tid & 7;
    int sgoff = srow * 128 + sch * 16;
    int sdoff = srow * 128 + ((sch ^ (srow & 7)) << 4);

    int i8 = lane & 7;
    int la = lane & 15, ca = lane >> 4;
    int rowoff = ((lane >> 4) << 3) + i8;
    int choff = (lane >> 3) & 1;
    int matq = lane >> 3;
    int vrowb = (((matq & 1) << 3) + i8) * 128;
    int chh = matq >> 1;

    // ---- prologue: Q + K/V stage0 via cp.async ----
    {
        const char* Qsrc = (const char*)(Qb + (size_t)q0 * 64);
        const char* Ksrc = (const char*)Kb;
        const char* Vsrc = (const char*)Vb;
#pragma unroll
        for (int i = 0; i < 4; ++i) {
            CP16(smb + 32768 + sdoff + i * 2048, Qsrc + sgoff + i * 2048);
            CP16(smb + sdoff + i * 2048,         Ksrc + sgoff + i * 2048);
            CP16(smb + 8192 + sdoff + i * 2048,  Vsrc + sgoff + i * 2048);
        }
        asm volatile("cp.async.commit_group;");
        asm volatile("cp.async.wait_group 0;" ::: "memory");
    }
    __syncthreads();

    unsigned qa[4][4];
    {
        int qrow = w * 16 + la;
#pragma unroll
        for (int s = 0; s < 4; ++s)
            ldsm4(qa[s][0], qa[s][1], qa[s][2], qa[s][3],
                  smb + 32768 + qrow * 128 + ((((2 * s + ca)) ^ (qrow & 7)) << 4));
    }

    float accO[8][4];
#pragma unroll
    for (int ot = 0; ot < 8; ++ot)
#pragma unroll
        for (int i = 0; i < 4; ++i) accO[ot][i] = 0.f;
    float lacc[4] = {0.f, 0.f, 0.f, 0.f};
    float m0 = -1e30f, m1 = -1e30f;

    const __half* G0 = g_G + ((size_t)bz * Nn + (q0 + w * 16 + g)) * Nn;
    const __half* G1 = G0 + (size_t)8 * Nn;
    const float SL2 = SCALE_F * LOG2E;
    const unsigned ONES = 0x3C003C00u;

    for (int kt = 0; kt < 32; ++kt) {
        unsigned kb = smb + (kt & 1) * 16384;
        unsigned vb = kb + 8192;

        if (kt < 31) {
            unsigned kbN = smb + ((kt + 1) & 1) * 16384;
            const char* Kn = (const char*)(Kb + (size_t)(kt + 1) * 4096);
            const char* Vn = (const char*)(Vb + (size_t)(kt + 1) * 4096);
#pragma unroll
            for (int i = 0; i < 4; ++i) {
                CP16(kbN + sdoff + i * 2048,        Kn + sgoff + i * 2048);
                CP16(kbN + 8192 + sdoff + i * 2048, Vn + sgoff + i * 2048);
            }
            asm volatile("cp.async.commit_group;");
        }

        __half2 gA[8], gB[8];
        {
            int cbase = kt * 64 + 2 * tg;
#pragma unroll
            for (int nt = 0; nt < 8; ++nt) {
                gA[nt] = *reinterpret_cast<const __half2*>(G0 + cbase + nt * 8);
                gB[nt] = *reinterpret_cast<const __half2*>(G1 + cbase + nt * 8);
            }
        }

        // ---- S = Q K^T ----
        float sacc[8][4];
#pragma unroll
        for (int nt = 0; nt < 8; ++nt)
#pragma unroll
            for (int i = 0; i < 4; ++i) sacc[nt][i] = 0.f;
#pragma unroll
        for (int s = 0; s < 4; ++s) {
#pragma unroll
            for (int ntp = 0; ntp < 4; ++ntp) {
                unsigned b0, b1, b2, b3;
                unsigned addr = kb + (unsigned)((16 * ntp + rowoff) * 128
                                + (((2 * s + choff) ^ i8) << 4));
                ldsm4(b0, b1, b2, b3, addr);
                mma_f16(sacc[2 * ntp][0], sacc[2 * ntp][1], sacc[2 * ntp][2], sacc[2 * ntp][3],
                        qa[s][0], qa[s][1], qa[s][2], qa[s][3], b0, b1);
                mma_f16(sacc[2 * ntp + 1][0], sacc[2 * ntp + 1][1], sacc[2 * ntp + 1][2], sacc[2 * ntp + 1][3],
                        qa[s][0], qa[s][1], qa[s][2], qa[s][3], b2, b3);
            }
        }

        // logits
#pragma unroll
        for (int nt = 0; nt < 8; ++nt) {
            float2 ga = __half22float2(gA[nt]);
            float2 gb2 = __half22float2(gB[nt]);
            sacc[nt][0] = sacc[nt][0] * SL2 + ga.x;
            sacc[nt][1] = sacc[nt][1] * SL2 + ga.y;
            sacc[nt][2] = sacc[nt][2] * SL2 + gb2.x;
            sacc[nt][3] = sacc[nt][3] * SL2 + gb2.y;
        }

        // online softmax max update
        float mn0 = m0, mn1 = m1;
#pragma unroll
        for (int nt = 0; nt < 8; ++nt) {
            mn0 = fmaxf(mn0, fmaxf(sacc[nt][0], sacc[nt][1]));
            mn1 = fmaxf(mn1, fmaxf(sacc[nt][2], sacc[nt][3]));
        }
        mn0 = fmaxf(mn0, __shfl_xor_sync(0xffffffffu, mn0, 1));
        mn0 = fmaxf(mn0, __shfl_xor_sync(0xffffffffu, mn0, 2));
        mn1 = fmaxf(mn1, __shfl_xor_sync(0xffffffffu, mn1, 1));
        mn1 = fmaxf(mn1, __shfl_xor_sync(0xffffffffu, mn1, 2));
        float al0 = exp2f(m0 - mn0), al1 = exp2f(m1 - mn1);
        m0 = mn0; m1 = mn1;
#pragma unroll
        for (int ot = 0; ot < 8; ++ot) {
            accO[ot][0] *= al0; accO[ot][1] *= al0;
            accO[ot][2] *= al1; accO[ot][3] *= al1;
        }
        lacc[0] *= al0; lacc[1] *= al0;
        lacc[2] *= al1; lacc[3] *= al1;

        // P = exp2(t - m) in fp16 pairs (these ARE the PV A-frags)
        unsigned pe[8], po[8];
#pragma unroll
        for (int nt = 0; nt < 8; ++nt) {
            pe[nt] = ex2h2(pack2(sacc[nt][0] - m0, sacc[nt][1] - m0));
            po[nt] = ex2h2(pack2(sacc[nt][2] - m1, sacc[nt][3] - m1));
        }

        // ---- O += P@V ; l += P@ones ----
#pragma unroll
        for (int s = 0; s < 4; ++s) {
            unsigned aP0 = pe[2 * s];
            unsigned aP1 = po[2 * s];
            unsigned aP2 = pe[2 * s + 1];
            unsigned aP3 = po[2 * s + 1];
            mma_f16(lacc[0], lacc[1], lacc[2], lacc[3],
                    aP0, aP1, aP2, aP3, ONES, ONES);
            unsigned base_s = vb + s * 2048 + vrowb;
#pragma unroll
            for (int otp = 0; otp < 4; ++otp) {
                unsigned b0, b1, b2, b3;
                ldsm4t(b0, b1, b2, b3, base_s + ((((2 * otp + chh) ^ i8)) << 4));
                mma_f16(accO[2 * otp][0], accO[2 * otp][1], accO[2 * otp][2], accO[2 * otp][3],
                        aP0, aP1, aP2, aP3, b0, b1);
                mma_f16(accO[2 * otp + 1][0], accO[2 * otp + 1][1], accO[2 * otp + 1][2], accO[2 * otp + 1][3],
                        aP0, aP1, aP2, aP3, b2, b3);
            }
        }

        if (kt < 31)
            asm volatile("cp.async.wait_group 0;" ::: "memory");
        __syncthreads();
    }

    float inv0 = 1.0f / lacc[0], inv1 = 1.0f / lacc[2];
    int qr0 = q0 + w * 16 + g, qr1 = qr0 + 8;
    __half* O0 = g_AO + ((size_t)(bz * Nn + qr0)) * DM + h * 64;
    __half* O1 = g_AO + ((size_t)(bz * Nn + qr1)) * DM + h * 64;
#pragma unroll
    for (int ot = 0; ot < 8; ++ot) {
        int d = ot * 8 + 2 * tg;
        *reinterpret_cast<__half2*>(O0 + d) = __floats2half2_rn(accO[ot][0] * inv0, accO[ot][1] * inv0);
        *reinterpret_cast<__half2*>(O1 + d) = __floats2half2_rn(accO[ot][2] * inv1, accO[ot][3] * inv1);
    }
}

// ============================================================
extern "C" void kernel_launch(void* const* d_in, const int* in_sizes, int n_in,
                              void* d_out, int out_size) {
    const float* Qin  = (const float*)d_in[0];
    const float* KVin = (const float*)d_in[1];
    const float* SC   = (const float*)d_in[2];
    const float* Wq   = (const float*)d_in[3];
    const float* Wqb  = (const float*)d_in[4];
    const float* Wk   = (const float*)d_in[5];
    const float* Wkb  = (const float*)d_in[6];
    const float* Wv   = (const float*)d_in[7];
    const float* Wvb  = (const float*)d_in[8];
    const float* gw   = (const float*)d_in[9];
    const float* gb   = (const float*)d_in[10];
    const float* Wo   = (const float*)d_in[11];
    const float* Wob  = (const float*)d_in[12];
    float* out = (float*)d_out;

    cudaFuncSetAttribute(gemm_h,       cudaFuncAttributeMaxDynamicSharedMemorySize, GEMMH_SMEM);
    cudaFuncSetAttribute(flash_kernel, cudaFuncAttributeMaxDynamicSharedMemorySize, FLASH_SMEM);

    // fused converts + gate in ONE launch (independent work co-scheduled)
    prep_all<<<25600, 256>>>(reinterpret_cast<const float4*>(Wq),
                             reinterpret_cast<const float4*>(Wk),
                             reinterpret_cast<const float4*>(Wv),
                             reinterpret_cast<const float4*>(Wo),
                             reinterpret_cast<const float4*>(Qin),
                             reinterpret_cast<const float4*>(KVin),
                             reinterpret_cast<const float4*>(SC), gw, gb);

    gemm_h<<<dim3(8, 64),  256, GEMMH_SMEM>>>(Wqb, nullptr, nullptr, 0, 0);
    gemm_h<<<dim3(16, 64), 256, GEMMH_SMEM>>>(Wkb, Wvb,     nullptr, 1, 4);

    flash_kernel<<<dim3(8, 32, 4), 128, FLASH_SMEM>>>();

    gemm_h<<<dim3(8, 64),  256, GEMMH_SMEM>>>(Wob, nullptr, out, 2, 3);
}